// round 1
// baseline (speedup 1.0000x reference)
#include <cuda_runtime.h>

// ---------------- problem constants ----------------
#define BB   2
#define TTT  2048
#define DM   512
#define NHD  8
#define DHD  64
#define NLAY 4
#define DI   2048
#define CIN  2048
#define NCLS 64
#define MR   (BB * TTT)   // 4096 token rows

// ---------------- scratch (device globals; no allocation allowed) ----------------
__device__ float g_xT[(size_t)BB * TTT * CIN];        // 33.5 MB  x transposed [b][t][c]
__device__ float g_h[(size_t)MR * DM];                // hidden state [b*T][d]
__device__ float g_tmp[(size_t)MR * DM];              // attn_out / ff2 out
__device__ float g_heads[(size_t)MR * 3 * DM];        // qkv [b*T][1536]
__device__ float g_qw[(size_t)MR * DM];               // q + r_w_bias
__device__ float g_qr[(size_t)MR * DM];               // q + r_r_bias
__device__ float g_rk[(size_t)TTT * DM];              // r_head_k [T][512]
__device__ float g_pos[(size_t)TTT * DM];             // pos_emb [T][512]
__device__ float g_ff[(size_t)MR * DI];               // ff hidden
__device__ float g_AC[(size_t)BB * NHD * TTT * TTT];  // 268 MB, AC then P (in place)
__device__ float g_BD[(size_t)BB * NHD * TTT * TTT];  // 268 MB, unshifted pos scores
__device__ float g_av[(size_t)MR * DM];               // attn vectors
__device__ float g_cls[(size_t)MR * NCLS];            // pre-transpose classifier out

// ---------------- dense GEMM: C[M,N] = A[M,K] * W[N,K]^T (+bias)(+relu) ----------------
// 128x128 tile, 256 threads, 8x8 per thread, K-tile 16.
__global__ void __launch_bounds__(256) gemm128(
    const float* __restrict__ A, int lda,
    const float* __restrict__ W, int ldb,
    const float* __restrict__ bias,
    float* __restrict__ C, int ldc,
    int M, int N, int K, int relu)
{
    __shared__ float As[128][17];
    __shared__ float Bs[128][17];
    const int tid = threadIdx.x;
    const int tx = tid & 15, ty = tid >> 4;
    const int m0 = blockIdx.y * 128, n0 = blockIdx.x * 128;

    float acc[8][8];
#pragma unroll
    for (int r = 0; r < 8; r++)
#pragma unroll
        for (int c = 0; c < 8; c++) acc[r][c] = 0.f;

    for (int k0 = 0; k0 < K; k0 += 16) {
#pragma unroll
        for (int i = 0; i < 2; i++) {
            int idx = tid + i * 256;       // 0..511
            int row = idx >> 2;            // 0..127
            int kq  = (idx & 3) * 4;       // 0,4,8,12
            float4 v = make_float4(0.f, 0.f, 0.f, 0.f);
            int m = m0 + row;
            if (m < M) v = *(const float4*)(A + (size_t)m * lda + k0 + kq);
            As[row][kq] = v.x; As[row][kq + 1] = v.y; As[row][kq + 2] = v.z; As[row][kq + 3] = v.w;
            float4 w = make_float4(0.f, 0.f, 0.f, 0.f);
            int n = n0 + row;
            if (n < N) w = *(const float4*)(W + (size_t)n * ldb + k0 + kq);
            Bs[row][kq] = w.x; Bs[row][kq + 1] = w.y; Bs[row][kq + 2] = w.z; Bs[row][kq + 3] = w.w;
        }
        __syncthreads();
#pragma unroll
        for (int kk = 0; kk < 16; kk++) {
            float a[8], b[8];
#pragma unroll
            for (int r = 0; r < 4; r++) {
                a[r]     = As[ty * 4 + r][kk];
                a[r + 4] = As[64 + ty * 4 + r][kk];
                b[r]     = Bs[tx * 4 + r][kk];
                b[r + 4] = Bs[64 + tx * 4 + r][kk];
            }
#pragma unroll
            for (int r = 0; r < 8; r++)
#pragma unroll
                for (int c = 0; c < 8; c++)
                    acc[r][c] += a[r] * b[c];
        }
        __syncthreads();
    }

#pragma unroll
    for (int r = 0; r < 8; r++) {
        int m = m0 + ((r < 4) ? (ty * 4 + r) : (64 + ty * 4 + (r - 4)));
        if (m >= M) continue;
#pragma unroll
        for (int c = 0; c < 8; c++) {
            int n = n0 + ((c < 4) ? (tx * 4 + c) : (64 + tx * 4 + (c - 4)));
            if (n >= N) continue;
            float v = acc[r][c];
            if (bias) v += bias[n];
            if (relu) v = fmaxf(v, 0.f);
            C[(size_t)m * ldc + n] = v;
        }
    }
}

// ---------------- batched attention GEMM: per (b,n), C = A[M,K] * B^T ----------------
// B element (n_out, k) at Bm[n_out*brs + k*bcs].  All dims multiples of 64.
__global__ void __launch_bounds__(256) gemm64(
    const float* __restrict__ A, size_t sAb, size_t sAn, int lda,
    const float* __restrict__ Bm, size_t sBb, size_t sBn, int brs, int bcs,
    float* __restrict__ C, size_t sCb, size_t sCn, int ldc,
    int M, int N, int K)
{
    const int bn = blockIdx.z;
    const int b = bn >> 3, n = bn & 7;
    A  += (size_t)b * sAb + (size_t)n * sAn;
    Bm += (size_t)b * sBb + (size_t)n * sBn;
    C  += (size_t)b * sCb + (size_t)n * sCn;

    __shared__ float As[64][65];
    __shared__ float Bs[64][65];
    const int tid = threadIdx.x;
    const int tx = tid & 15, ty = tid >> 4;
    const int m0 = blockIdx.y * 64, n0 = blockIdx.x * 64;

    float acc[4][4];
#pragma unroll
    for (int r = 0; r < 4; r++)
#pragma unroll
        for (int c = 0; c < 4; c++) acc[r][c] = 0.f;

    for (int k0 = 0; k0 < K; k0 += 64) {
#pragma unroll
        for (int i = 0; i < 4; i++) {
            int idx = tid + i * 256;       // 0..1023
            int row = idx >> 4;            // 0..63
            int kq  = (idx & 15) * 4;      // 0..60
            float4 v = *(const float4*)(A + (size_t)(m0 + row) * lda + k0 + kq);
            As[row][kq] = v.x; As[row][kq + 1] = v.y; As[row][kq + 2] = v.z; As[row][kq + 3] = v.w;
        }
        if (bcs == 1) {
#pragma unroll
            for (int i = 0; i < 4; i++) {
                int idx = tid + i * 256;
                int row = idx >> 4;
                int kq  = (idx & 15) * 4;
                float4 v = *(const float4*)(Bm + (size_t)(n0 + row) * brs + k0 + kq);
                Bs[row][kq] = v.x; Bs[row][kq + 1] = v.y; Bs[row][kq + 2] = v.z; Bs[row][kq + 3] = v.w;
            }
        } else {
#pragma unroll
            for (int i = 0; i < 16; i++) {
                int idx = tid + i * 256;   // 0..4095
                int k = idx >> 6, nn = idx & 63;
                Bs[nn][k] = Bm[(size_t)(n0 + nn) * brs + (size_t)(k0 + k) * bcs];
            }
        }
        __syncthreads();
#pragma unroll 8
        for (int kk = 0; kk < 64; kk++) {
            float a[4], bb[4];
#pragma unroll
            for (int r = 0; r < 4; r++) {
                a[r]  = As[ty * 4 + r][kk];
                bb[r] = Bs[tx * 4 + r][kk];
            }
#pragma unroll
            for (int r = 0; r < 4; r++)
#pragma unroll
                for (int c = 0; c < 4; c++)
                    acc[r][c] += a[r] * bb[c];
        }
        __syncthreads();
    }
#pragma unroll
    for (int r = 0; r < 4; r++)
#pragma unroll
        for (int c = 0; c < 4; c++)
            C[(size_t)(m0 + ty * 4 + r) * ldc + n0 + tx * 4 + c] = acc[r][c];
}

// ---------------- fused rel-shift + scale + softmax (row-wise over keys) ----------------
// rel_shift(Bx)[i,j] = Bx[i, T-1-i+j] (j<=i) ; 0 (j==i+1) ; Bx[i+1, j-i-2] (j>i+1)
__global__ void __launch_bounds__(256) softmax_shift(
    float* __restrict__ P, const float* __restrict__ BD, float scale)
{
    const int i  = blockIdx.x;
    const int bn = blockIdx.y;
    float* ac = P + ((size_t)bn * TTT + i) * TTT;
    const float* bd = BD + (size_t)bn * TTT * TTT;
    const int tid = threadIdx.x;

    float v[8];
    float mx = -1e30f;
#pragma unroll
    for (int jj = 0; jj < 8; jj++) {
        int j = tid + jj * 256;
        float y;
        if (j <= i)           y = bd[(size_t)i * TTT + (TTT - 1 - i + j)];
        else if (j == i + 1)  y = 0.f;
        else                  y = bd[(size_t)(i + 1) * TTT + (j - i - 2)];
        float s = (ac[j] + y) * scale;
        v[jj] = s;
        mx = fmaxf(mx, s);
    }

    __shared__ float red[8];
#pragma unroll
    for (int o = 16; o > 0; o >>= 1) mx = fmaxf(mx, __shfl_xor_sync(0xffffffffu, mx, o));
    if ((tid & 31) == 0) red[tid >> 5] = mx;
    __syncthreads();
    mx = red[0];
#pragma unroll
    for (int w = 1; w < 8; w++) mx = fmaxf(mx, red[w]);
    __syncthreads();

    float sum = 0.f;
#pragma unroll
    for (int jj = 0; jj < 8; jj++) { v[jj] = __expf(v[jj] - mx); sum += v[jj]; }
#pragma unroll
    for (int o = 16; o > 0; o >>= 1) sum += __shfl_xor_sync(0xffffffffu, sum, o);
    if ((tid & 31) == 0) red[tid >> 5] = sum;
    __syncthreads();
    sum = 0.f;
#pragma unroll
    for (int w = 0; w < 8; w++) sum += red[w];
    float inv = 1.f / sum;
#pragma unroll
    for (int jj = 0; jj < 8; jj++) ac[tid + jj * 256] = v[jj] * inv;
}

// ---------------- residual add + LayerNorm over d=512 ----------------
__global__ void __launch_bounds__(128) add_ln(
    float* __restrict__ h, const float* __restrict__ a,
    const float* __restrict__ gs, const float* __restrict__ gb)
{
    const int row = blockIdx.x, tid = threadIdx.x;
    float* hp = h + (size_t)row * DM;
    const float* ap = a + (size_t)row * DM;
    float v[4];
    float s = 0.f;
#pragma unroll
    for (int j = 0; j < 4; j++) { int c = tid + j * 128; v[j] = hp[c] + ap[c]; s += v[j]; }

    __shared__ float red[8];
#pragma unroll
    for (int o = 16; o > 0; o >>= 1) s += __shfl_xor_sync(0xffffffffu, s, o);
    if ((tid & 31) == 0) red[tid >> 5] = s;
    __syncthreads();
    float mean = (red[0] + red[1] + red[2] + red[3]) * (1.f / 512.f);

    float var = 0.f;
#pragma unroll
    for (int j = 0; j < 4; j++) { float d = v[j] - mean; var += d * d; }
#pragma unroll
    for (int o = 16; o > 0; o >>= 1) var += __shfl_xor_sync(0xffffffffu, var, o);
    if ((tid & 31) == 0) red[4 + (tid >> 5)] = var;
    __syncthreads();
    var = (red[4] + red[5] + red[6] + red[7]) * (1.f / 512.f);
    float rs = rsqrtf(var + 1e-5f);
#pragma unroll
    for (int j = 0; j < 4; j++) {
        int c = tid + j * 128;
        hp[c] = (v[j] - mean) * rs * gs[c] + gb[c];
    }
}

// ---------------- small helpers ----------------
__global__ void __launch_bounds__(256) make_qwr(
    const float* __restrict__ heads, const float* __restrict__ rw,
    const float* __restrict__ rr, float* __restrict__ qw, float* __restrict__ qr)
{
    int idx = blockIdx.x * 256 + threadIdx.x;      // over MR*DM
    int m = idx >> 9, c = idx & 511;
    float q = heads[(size_t)m * 1536 + c];
    qw[idx] = q + rw[c];
    qr[idx] = q + rr[c];
}

__global__ void __launch_bounds__(256) pos_kernel(float* __restrict__ pos)
{
    int p = blockIdx.x;
    int f = threadIdx.x;                           // 0..255
    float ps = (float)(TTT - 1 - p);
    float invf = 1.0f / powf(10000.0f, (float)(2 * f) / (float)DM);
    float ang = ps * invf;
    pos[(size_t)p * DM + f]       = sinf(ang);
    pos[(size_t)p * DM + 256 + f] = cosf(ang);
}

// x[b][c][t] -> xT[b][t][c]
__global__ void transpose_x(const float* __restrict__ x, float* __restrict__ xT)
{
    __shared__ float tile[32][33];
    int b = blockIdx.z;
    int t0 = blockIdx.x * 32, c0 = blockIdx.y * 32;
    int tx = threadIdx.x, ty = threadIdx.y;
#pragma unroll
    for (int i = 0; i < 4; i++) {
        int c = c0 + ty + i * 8;
        tile[ty + i * 8][tx] = x[((size_t)b * CIN + c) * TTT + t0 + tx];
    }
    __syncthreads();
#pragma unroll
    for (int i = 0; i < 4; i++) {
        int t = t0 + ty + i * 8;
        xT[((size_t)b * TTT + t) * CIN + c0 + tx] = tile[tx][ty + i * 8];
    }
}

// cls_tmp[(b*T + t)*64 + k] -> out[b][k][t]
__global__ void transpose_cls(const float* __restrict__ tmp, float* __restrict__ outp)
{
    __shared__ float tile[32][33];
    int b = blockIdx.z;
    int t0 = blockIdx.x * 32, k0 = blockIdx.y * 32;
    int tx = threadIdx.x, ty = threadIdx.y;
#pragma unroll
    for (int i = 0; i < 4; i++) {
        int t = t0 + ty + i * 8;
        tile[ty + i * 8][tx] = tmp[((size_t)b * TTT + t) * NCLS + k0 + tx];
    }
    __syncthreads();
#pragma unroll
    for (int i = 0; i < 4; i++) {
        int k = k0 + ty + i * 8;
        outp[((size_t)b * NCLS + k) * TTT + t0 + tx] = tile[tx][ty + i * 8];
    }
}

// ---------------- host orchestration ----------------
extern "C" void kernel_launch(void* const* d_in, const int* in_sizes, int n_in,
                              void* d_out, int out_size)
{
    const float* x        = (const float*)d_in[0];
    const float* emb_w    = (const float*)d_in[1];
    const float* emb_b    = (const float*)d_in[2];
    const float* r_w_bias = (const float*)d_in[3];
    const float* r_r_bias = (const float*)d_in[4];
    const float* qkv_w    = (const float*)d_in[5];
    const float* qkv_b    = (const float*)d_in[6];
    const float* r_proj_w = (const float*)d_in[7];
    const float* o_w      = (const float*)d_in[8];
    const float* ln1_s    = (const float*)d_in[9];
    const float* ln1_b    = (const float*)d_in[10];
    const float* ff1_w    = (const float*)d_in[11];
    const float* ff1_b    = (const float*)d_in[12];
    const float* ff2_w    = (const float*)d_in[13];
    const float* ff2_b    = (const float*)d_in[14];
    const float* ln2_s    = (const float*)d_in[15];
    const float* ln2_b    = (const float*)d_in[16];
    const float* cls_w    = (const float*)d_in[17];
    const float* cls_b    = (const float*)d_in[18];
    float* outp = (float*)d_out;

    float *xT, *h, *tmp, *heads, *qw, *qr, *rk, *pos, *ff, *AC, *BD, *av, *cls;
    cudaGetSymbolAddress((void**)&xT, g_xT);
    cudaGetSymbolAddress((void**)&h, g_h);
    cudaGetSymbolAddress((void**)&tmp, g_tmp);
    cudaGetSymbolAddress((void**)&heads, g_heads);
    cudaGetSymbolAddress((void**)&qw, g_qw);
    cudaGetSymbolAddress((void**)&qr, g_qr);
    cudaGetSymbolAddress((void**)&rk, g_rk);
    cudaGetSymbolAddress((void**)&pos, g_pos);
    cudaGetSymbolAddress((void**)&ff, g_ff);
    cudaGetSymbolAddress((void**)&AC, g_AC);
    cudaGetSymbolAddress((void**)&BD, g_BD);
    cudaGetSymbolAddress((void**)&av, g_av);
    cudaGetSymbolAddress((void**)&cls, g_cls);

    const float scale = 1.0f / 8.0f;   // 1/sqrt(64)

    transpose_x<<<dim3(TTT / 32, CIN / 32, BB), dim3(32, 8)>>>(x, xT);
    pos_kernel<<<TTT, 256>>>(pos);

    // embed: h = xT @ emb_w^T + emb_b   [4096,512] = [4096,2048] x [512,2048]^T
    gemm128<<<dim3((DM + 127) / 128, MR / 128), 256>>>(
        xT, CIN, emb_w, CIN, emb_b, h, DM, MR, DM, CIN, 0);

    for (int l = 0; l < NLAY; l++) {
        const float* qkvW = qkv_w + (size_t)l * 3 * DM * DM;
        const float* qkvB = qkv_b + (size_t)l * 3 * DM;
        const float* rW   = r_proj_w + (size_t)l * DM * DM;
        const float* oW   = o_w + (size_t)l * DM * DM;
        const float* f1W  = ff1_w + (size_t)l * DI * DM;
        const float* f1B  = ff1_b + (size_t)l * DI;
        const float* f2W  = ff2_w + (size_t)l * DM * DI;
        const float* f2B  = ff2_b + (size_t)l * DM;

        // heads = h @ qkv_w^T + b   [4096,1536]
        gemm128<<<dim3(12, MR / 128), 256>>>(h, DM, qkvW, DM, qkvB, heads, 3 * DM, MR, 3 * DM, DM, 0);

        // qw = q + r_w_bias ; qr = q + r_r_bias
        make_qwr<<<(MR * DM) / 256, 256>>>(heads, r_w_bias, r_r_bias, qw, qr);

        // rk = pos @ r_proj_w^T   [2048,512]
        gemm128<<<dim3(4, TTT / 128), 256>>>(pos, DM, rW, DM, nullptr, rk, DM, TTT, DM, DM, 0);

        // AC[bn] = qw_bn @ K_bn^T    (M=T, N=T, K=64)
        gemm64<<<dim3(TTT / 64, TTT / 64, BB * NHD), 256>>>(
            qw, (size_t)TTT * DM, 64, DM,
            heads + DM, (size_t)TTT * 3 * DM, 64, 3 * DM, 1,
            AC, (size_t)NHD * TTT * TTT, (size_t)TTT * TTT, TTT,
            TTT, TTT, 64);

        // BD[bn] = qr_bn @ rk_n^T
        gemm64<<<dim3(TTT / 64, TTT / 64, BB * NHD), 256>>>(
            qr, (size_t)TTT * DM, 64, DM,
            rk, 0, 64, DM, 1,
            BD, (size_t)NHD * TTT * TTT, (size_t)TTT * TTT, TTT,
            TTT, TTT, 64);

        // P = softmax(scale*(AC + shift(BD)))  (in place over AC)
        softmax_shift<<<dim3(TTT, BB * NHD), 256>>>(AC, BD, scale);

        // av[bn] = P @ V   (M=T, N=64, K=T); B(n=d, k=j) = V[j,d] -> brs=1, bcs=1536
        gemm64<<<dim3(1, TTT / 64, BB * NHD), 256>>>(
            AC, (size_t)NHD * TTT * TTT, (size_t)TTT * TTT, TTT,
            heads + 2 * DM, (size_t)TTT * 3 * DM, 64, 1, 3 * DM,
            av, (size_t)TTT * DM, 64, DM,
            TTT, 64, TTT);

        // attn_out = av @ o_w^T
        gemm128<<<dim3(4, MR / 128), 256>>>(av, DM, oW, DM, nullptr, tmp, DM, MR, DM, DM, 0);

        // h = LN(h + attn_out)
        add_ln<<<MR, 128>>>(h, tmp, ln1_s + l * DM, ln1_b + l * DM);

        // ff = relu(h @ ff1_w^T + b)
        gemm128<<<dim3(DI / 128, MR / 128), 256>>>(h, DM, f1W, DM, f1B, ff, DI, MR, DI, DM, 1);

        // tmp = ff @ ff2_w^T + b
        gemm128<<<dim3(4, MR / 128), 256>>>(ff, DI, f2W, DI, f2B, tmp, DM, MR, DM, DI, 0);

        // h = LN(h + ff_out)
        add_ln<<<MR, 128>>>(h, tmp, ln2_s + l * DM, ln2_b + l * DM);
    }

    // cls = h @ cls_w^T + b   [4096,64]
    gemm128<<<dim3(1, MR / 128), 256>>>(h, DM, cls_w, DM, cls_b, cls, NCLS, MR, NCLS, DM, 0);

    // out[b][k][t]
    transpose_cls<<<dim3(TTT / 32, NCLS / 32, BB), dim3(32, 8)>>>(cls, outp);
}

// round 2
// speedup vs baseline: 1.5768x; 1.5768x over previous
#include <cuda_runtime.h>

// ---------------- problem constants ----------------
#define BB   2
#define TTT  2048
#define DM   512
#define NHD  8
#define DHD  64
#define NLAY 4
#define DI   2048
#define CIN  2048
#define NCLS 64
#define MR   (BB * TTT)   // 4096 token rows

// ---------------- scratch (device globals; no allocation allowed) ----------------
__device__ float g_xT[(size_t)BB * TTT * CIN];
__device__ float g_h[(size_t)MR * DM];
__device__ float g_tmp[(size_t)MR * DM];
__device__ float g_heads[(size_t)MR * 3 * DM];
__device__ float g_qw[(size_t)MR * DM];
__device__ float g_qr[(size_t)MR * DM];
__device__ float g_rk[(size_t)TTT * DM];
__device__ float g_pos[(size_t)TTT * DM];
__device__ float g_ff[(size_t)MR * DI];
__device__ float g_AC[(size_t)BB * NHD * TTT * TTT];
__device__ float g_BD[(size_t)BB * NHD * TTT * TTT];
__device__ float g_av[(size_t)MR * DM];
__device__ float g_cls[(size_t)MR * NCLS];

// ---------------- tf32 helpers ----------------
__device__ __forceinline__ unsigned f2tf(float x) {
    unsigned u;
    asm("cvt.rna.tf32.f32 %0, %1;" : "=r"(u) : "f"(x));
    return u;
}

__device__ __forceinline__ void mma_tf32(float* c, const unsigned* a, const unsigned* b) {
    asm volatile(
        "mma.sync.aligned.m16n8k8.row.col.f32.tf32.tf32.f32 "
        "{%0,%1,%2,%3}, {%4,%5,%6,%7}, {%8,%9}, {%0,%1,%2,%3};"
        : "+f"(c[0]), "+f"(c[1]), "+f"(c[2]), "+f"(c[3])
        : "r"(a[0]), "r"(a[1]), "r"(a[2]), "r"(a[3]), "r"(b[0]), "r"(b[1]));
}

// ---------------- TF32 tensor-core GEMM ----------------
// C[M,N] = A[M,K] @ B^T (+bias)(+relu).
// A row-major [m][k]. bTrans=0: B[n][k] (k contiguous). bTrans=1: B[k][n] (n contiguous).
// Optional batching over blockIdx.z = b*8+n with explicit strides.
// M % 128 == 0, K % 32 == 0 required. N predicated.
__global__ void __launch_bounds__(256) gemm_tf32(
    const float* __restrict__ A, int lda, size_t sAb, size_t sAn,
    const float* __restrict__ B, int ldb, size_t sBb, size_t sBn,
    const float* __restrict__ bias,
    float* __restrict__ C, int ldc, size_t sCb, size_t sCn,
    int M, int N, int K, int relu, int bTrans)
{
    const int z = blockIdx.z, zb = z >> 3, zn = z & 7;
    A += (size_t)zb * sAb + (size_t)zn * sAn;
    B += (size_t)zb * sBb + (size_t)zn * sBn;
    C += (size_t)zb * sCb + (size_t)zn * sCn;

    __shared__ unsigned As[128][36];
    __shared__ unsigned Bs[128][36];

    const int tid = threadIdx.x;
    const int warp = tid >> 5, lane = tid & 31;
    const int wm = warp >> 2, wn = warp & 3;     // 2 x 4 warp grid; warp tile 64 x 32
    const int g = lane >> 2, tg = lane & 3;
    const int m0 = blockIdx.y * 128, n0 = blockIdx.x * 128;

    float acc[4][4][4];
#pragma unroll
    for (int mt = 0; mt < 4; mt++)
#pragma unroll
        for (int nt = 0; nt < 4; nt++)
#pragma unroll
            for (int i = 0; i < 4; i++) acc[mt][nt][i] = 0.f;

    for (int k0 = 0; k0 < K; k0 += 32) {
        // ---- load A tile [128][32]
#pragma unroll
        for (int i = 0; i < 4; i++) {
            int idx = tid + i * 256;        // 0..1023 float4 slots
            int row = idx >> 3;
            int kq = (idx & 7) * 4;
            float4 v = *(const float4*)(A + (size_t)(m0 + row) * lda + k0 + kq);
            As[row][kq + 0] = f2tf(v.x);
            As[row][kq + 1] = f2tf(v.y);
            As[row][kq + 2] = f2tf(v.z);
            As[row][kq + 3] = f2tf(v.w);
        }
        // ---- load B tile -> Bs[n][k]
        if (!bTrans) {
#pragma unroll
            for (int i = 0; i < 4; i++) {
                int idx = tid + i * 256;
                int row = idx >> 3;
                int kq = (idx & 7) * 4;
                float4 v = make_float4(0.f, 0.f, 0.f, 0.f);
                if (n0 + row < N) v = *(const float4*)(B + (size_t)(n0 + row) * ldb + k0 + kq);
                Bs[row][kq + 0] = f2tf(v.x);
                Bs[row][kq + 1] = f2tf(v.y);
                Bs[row][kq + 2] = f2tf(v.z);
                Bs[row][kq + 3] = f2tf(v.w);
            }
        } else {
#pragma unroll
            for (int i = 0; i < 16; i++) {
                int idx = tid + i * 256;     // 0..4095
                int kk = idx >> 7, nn = idx & 127;
                float v = 0.f;
                if (n0 + nn < N) v = B[(size_t)(k0 + kk) * ldb + n0 + nn];
                Bs[nn][kk] = f2tf(v);
            }
        }
        __syncthreads();

#pragma unroll
        for (int ks = 0; ks < 4; ks++) {
            const int kk = ks * 8;
            unsigned a[4][4], bb[4][2];
#pragma unroll
            for (int mt = 0; mt < 4; mt++) {
                int r = wm * 64 + mt * 16;
                a[mt][0] = As[r + g][kk + tg];
                a[mt][1] = As[r + g + 8][kk + tg];
                a[mt][2] = As[r + g][kk + tg + 4];
                a[mt][3] = As[r + g + 8][kk + tg + 4];
            }
#pragma unroll
            for (int nt = 0; nt < 4; nt++) {
                int c = wn * 32 + nt * 8;
                bb[nt][0] = Bs[c + g][kk + tg];
                bb[nt][1] = Bs[c + g][kk + tg + 4];
            }
#pragma unroll
            for (int mt = 0; mt < 4; mt++)
#pragma unroll
                for (int nt = 0; nt < 4; nt++)
                    mma_tf32(acc[mt][nt], a[mt], bb[nt]);
        }
        __syncthreads();
    }

    // ---- epilogue
#pragma unroll
    for (int mt = 0; mt < 4; mt++) {
        int r0 = m0 + wm * 64 + mt * 16 + g;
#pragma unroll
        for (int nt = 0; nt < 4; nt++) {
            int c0 = n0 + wn * 32 + nt * 8 + tg * 2;
            if (c0 < N) {
                float b0v = bias ? bias[c0] : 0.f;
                float b1v = bias ? bias[c0 + 1] : 0.f;
                float v0 = acc[mt][nt][0] + b0v;
                float v1 = acc[mt][nt][1] + b1v;
                float v2 = acc[mt][nt][2] + b0v;
                float v3 = acc[mt][nt][3] + b1v;
                if (relu) {
                    v0 = fmaxf(v0, 0.f); v1 = fmaxf(v1, 0.f);
                    v2 = fmaxf(v2, 0.f); v3 = fmaxf(v3, 0.f);
                }
                *(float2*)(C + (size_t)r0 * ldc + c0) = make_float2(v0, v1);
                *(float2*)(C + (size_t)(r0 + 8) * ldc + c0) = make_float2(v2, v3);
            }
        }
    }
}

// ---------------- fused rel-shift + scale + softmax ----------------
// rel_shift(Bx)[i,j] = Bx[i, T-1-i+j] (j<=i) ; 0 (j==i+1) ; Bx[i+1, j-i-2] (j>i+1)
__global__ void __launch_bounds__(256) softmax_shift(
    float* __restrict__ P, const float* __restrict__ BD, float scale)
{
    const int i  = blockIdx.x;
    const int bn = blockIdx.y;
    float* ac = P + ((size_t)bn * TTT + i) * TTT;
    const float* bd = BD + (size_t)bn * TTT * TTT;
    const int tid = threadIdx.x;

    float v[8];
    float mx = -1e30f;
#pragma unroll
    for (int jj = 0; jj < 8; jj++) {
        int j = tid + jj * 256;
        float y;
        if (j <= i)           y = bd[(size_t)i * TTT + (TTT - 1 - i + j)];
        else if (j == i + 1)  y = 0.f;
        else                  y = bd[(size_t)(i + 1) * TTT + (j - i - 2)];
        float s = (ac[j] + y) * scale;
        v[jj] = s;
        mx = fmaxf(mx, s);
    }

    __shared__ float red[8];
#pragma unroll
    for (int o = 16; o > 0; o >>= 1) mx = fmaxf(mx, __shfl_xor_sync(0xffffffffu, mx, o));
    if ((tid & 31) == 0) red[tid >> 5] = mx;
    __syncthreads();
    mx = red[0];
#pragma unroll
    for (int w = 1; w < 8; w++) mx = fmaxf(mx, red[w]);
    __syncthreads();

    float sum = 0.f;
#pragma unroll
    for (int jj = 0; jj < 8; jj++) { v[jj] = __expf(v[jj] - mx); sum += v[jj]; }
#pragma unroll
    for (int o = 16; o > 0; o >>= 1) sum += __shfl_xor_sync(0xffffffffu, sum, o);
    if ((tid & 31) == 0) red[tid >> 5] = sum;
    __syncthreads();
    sum = 0.f;
#pragma unroll
    for (int w = 0; w < 8; w++) sum += red[w];
    float inv = 1.f / sum;
#pragma unroll
    for (int jj = 0; jj < 8; jj++) ac[tid + jj * 256] = v[jj] * inv;
}

// ---------------- residual add + LayerNorm over d=512 ----------------
__global__ void __launch_bounds__(128) add_ln(
    float* __restrict__ h, const float* __restrict__ a,
    const float* __restrict__ gs, const float* __restrict__ gb)
{
    const int row = blockIdx.x, tid = threadIdx.x;
    float* hp = h + (size_t)row * DM;
    const float* ap = a + (size_t)row * DM;
    float v[4];
    float s = 0.f;
#pragma unroll
    for (int j = 0; j < 4; j++) { int c = tid + j * 128; v[j] = hp[c] + ap[c]; s += v[j]; }

    __shared__ float red[8];
#pragma unroll
    for (int o = 16; o > 0; o >>= 1) s += __shfl_xor_sync(0xffffffffu, s, o);
    if ((tid & 31) == 0) red[tid >> 5] = s;
    __syncthreads();
    float mean = (red[0] + red[1] + red[2] + red[3]) * (1.f / 512.f);

    float var = 0.f;
#pragma unroll
    for (int j = 0; j < 4; j++) { float d = v[j] - mean; var += d * d; }
#pragma unroll
    for (int o = 16; o > 0; o >>= 1) var += __shfl_xor_sync(0xffffffffu, var, o);
    if ((tid & 31) == 0) red[4 + (tid >> 5)] = var;
    __syncthreads();
    var = (red[4] + red[5] + red[6] + red[7]) * (1.f / 512.f);
    float rs = rsqrtf(var + 1e-5f);
#pragma unroll
    for (int j = 0; j < 4; j++) {
        int c = tid + j * 128;
        hp[c] = (v[j] - mean) * rs * gs[c] + gb[c];
    }
}

// ---------------- small helpers ----------------
__global__ void __launch_bounds__(256) make_qwr(
    const float* __restrict__ heads, const float* __restrict__ rw,
    const float* __restrict__ rr, float* __restrict__ qw, float* __restrict__ qr)
{
    int idx = blockIdx.x * 256 + threadIdx.x;
    int m = idx >> 9, c = idx & 511;
    float q = heads[(size_t)m * 1536 + c];
    qw[idx] = q + rw[c];
    qr[idx] = q + rr[c];
}

__global__ void __launch_bounds__(256) pos_kernel(float* __restrict__ pos)
{
    int p = blockIdx.x;
    int f = threadIdx.x;
    float ps = (float)(TTT - 1 - p);
    float invf = 1.0f / powf(10000.0f, (float)(2 * f) / (float)DM);
    float ang = ps * invf;
    pos[(size_t)p * DM + f]       = sinf(ang);
    pos[(size_t)p * DM + 256 + f] = cosf(ang);
}

__global__ void transpose_x(const float* __restrict__ x, float* __restrict__ xT)
{
    __shared__ float tile[32][33];
    int b = blockIdx.z;
    int t0 = blockIdx.x * 32, c0 = blockIdx.y * 32;
    int tx = threadIdx.x, ty = threadIdx.y;
#pragma unroll
    for (int i = 0; i < 4; i++) {
        int c = c0 + ty + i * 8;
        tile[ty + i * 8][tx] = x[((size_t)b * CIN + c) * TTT + t0 + tx];
    }
    __syncthreads();
#pragma unroll
    for (int i = 0; i < 4; i++) {
        int t = t0 + ty + i * 8;
        xT[((size_t)b * TTT + t) * CIN + c0 + tx] = tile[tx][ty + i * 8];
    }
}

__global__ void transpose_cls(const float* __restrict__ tmp, float* __restrict__ outp)
{
    __shared__ float tile[32][33];
    int b = blockIdx.z;
    int t0 = blockIdx.x * 32, k0 = blockIdx.y * 32;
    int tx = threadIdx.x, ty = threadIdx.y;
#pragma unroll
    for (int i = 0; i < 4; i++) {
        int t = t0 + ty + i * 8;
        tile[ty + i * 8][tx] = tmp[((size_t)b * TTT + t) * NCLS + k0 + tx];
    }
    __syncthreads();
#pragma unroll
    for (int i = 0; i < 4; i++) {
        int k = k0 + ty + i * 8;
        outp[((size_t)b * NCLS + k) * TTT + t0 + tx] = tile[tx][ty + i * 8];
    }
}

// ---------------- host orchestration ----------------
extern "C" void kernel_launch(void* const* d_in, const int* in_sizes, int n_in,
                              void* d_out, int out_size)
{
    const float* x        = (const float*)d_in[0];
    const float* emb_w    = (const float*)d_in[1];
    const float* emb_b    = (const float*)d_in[2];
    const float* r_w_bias = (const float*)d_in[3];
    const float* r_r_bias = (const float*)d_in[4];
    const float* qkv_w    = (const float*)d_in[5];
    const float* qkv_b    = (const float*)d_in[6];
    const float* r_proj_w = (const float*)d_in[7];
    const float* o_w      = (const float*)d_in[8];
    const float* ln1_s    = (const float*)d_in[9];
    const float* ln1_b    = (const float*)d_in[10];
    const float* ff1_w    = (const float*)d_in[11];
    const float* ff1_b    = (const float*)d_in[12];
    const float* ff2_w    = (const float*)d_in[13];
    const float* ff2_b    = (const float*)d_in[14];
    const float* ln2_s    = (const float*)d_in[15];
    const float* ln2_b    = (const float*)d_in[16];
    const float* cls_w    = (const float*)d_in[17];
    const float* cls_b    = (const float*)d_in[18];
    float* outp = (float*)d_out;

    float *xT, *h, *tmp, *heads, *qw, *qr, *rk, *pos, *ff, *AC, *BD, *av, *cls;
    cudaGetSymbolAddress((void**)&xT, g_xT);
    cudaGetSymbolAddress((void**)&h, g_h);
    cudaGetSymbolAddress((void**)&tmp, g_tmp);
    cudaGetSymbolAddress((void**)&heads, g_heads);
    cudaGetSymbolAddress((void**)&qw, g_qw);
    cudaGetSymbolAddress((void**)&qr, g_qr);
    cudaGetSymbolAddress((void**)&rk, g_rk);
    cudaGetSymbolAddress((void**)&pos, g_pos);
    cudaGetSymbolAddress((void**)&ff, g_ff);
    cudaGetSymbolAddress((void**)&AC, g_AC);
    cudaGetSymbolAddress((void**)&BD, g_BD);
    cudaGetSymbolAddress((void**)&av, g_av);
    cudaGetSymbolAddress((void**)&cls, g_cls);

    const float scale = 1.0f / 8.0f;

    transpose_x<<<dim3(TTT / 32, CIN / 32, BB), dim3(32, 8)>>>(x, xT);
    pos_kernel<<<TTT, 256>>>(pos);

    // embed: h = xT @ emb_w^T + emb_b
    gemm_tf32<<<dim3(4, 32, 1), 256>>>(
        xT, CIN, 0, 0, emb_w, CIN, 0, 0, emb_b, h, DM, 0, 0, MR, DM, CIN, 0, 0);

    for (int l = 0; l < NLAY; l++) {
        const float* qkvW = qkv_w + (size_t)l * 3 * DM * DM;
        const float* qkvB = qkv_b + (size_t)l * 3 * DM;
        const float* rW   = r_proj_w + (size_t)l * DM * DM;
        const float* oW   = o_w + (size_t)l * DM * DM;
        const float* f1W  = ff1_w + (size_t)l * DI * DM;
        const float* f1B  = ff1_b + (size_t)l * DI;
        const float* f2W  = ff2_w + (size_t)l * DM * DI;
        const float* f2B  = ff2_b + (size_t)l * DM;

        // heads = h @ qkv_w^T + b
        gemm_tf32<<<dim3(12, 32, 1), 256>>>(
            h, DM, 0, 0, qkvW, DM, 0, 0, qkvB, heads, 3 * DM, 0, 0, MR, 3 * DM, DM, 0, 0);

        make_qwr<<<(MR * DM) / 256, 256>>>(heads, r_w_bias, r_r_bias, qw, qr);

        // rk = pos @ r_proj_w^T
        gemm_tf32<<<dim3(4, 16, 1), 256>>>(
            pos, DM, 0, 0, rW, DM, 0, 0, nullptr, rk, DM, 0, 0, TTT, DM, DM, 0, 0);

        // AC[b,n] = qw @ K^T
        gemm_tf32<<<dim3(16, 16, BB * NHD), 256>>>(
            qw, DM, (size_t)TTT * DM, 64,
            heads + DM, 3 * DM, (size_t)TTT * 3 * DM, 64,
            nullptr,
            AC, TTT, (size_t)NHD * TTT * TTT, (size_t)TTT * TTT,
            TTT, TTT, 64, 0, 0);

        // BD[b,n] = qr @ rk_n^T
        gemm_tf32<<<dim3(16, 16, BB * NHD), 256>>>(
            qr, DM, (size_t)TTT * DM, 64,
            rk, DM, 0, 64,
            nullptr,
            BD, TTT, (size_t)NHD * TTT * TTT, (size_t)TTT * TTT,
            TTT, TTT, 64, 0, 0);

        // P = softmax(scale * (AC + shift(BD)))  in place on AC
        softmax_shift<<<dim3(TTT, BB * NHD), 256>>>(AC, BD, scale);

        // av[b,n] = P @ V   (B is [k][n]: V rows are keys, cols are dhead)
        gemm_tf32<<<dim3(1, 16, BB * NHD), 256>>>(
            AC, TTT, (size_t)NHD * TTT * TTT, (size_t)TTT * TTT,
            heads + 2 * DM, 3 * DM, (size_t)TTT * 3 * DM, 64,
            nullptr,
            av, DM, (size_t)TTT * DM, 64,
            TTT, 64, TTT, 0, 1);

        // attn_out = av @ o_w^T
        gemm_tf32<<<dim3(4, 32, 1), 256>>>(
            av, DM, 0, 0, oW, DM, 0, 0, nullptr, tmp, DM, 0, 0, MR, DM, DM, 0, 0);

        add_ln<<<MR, 128>>>(h, tmp, ln1_s + l * DM, ln1_b + l * DM);

        // ff = relu(h @ ff1_w^T + b)
        gemm_tf32<<<dim3(16, 32, 1), 256>>>(
            h, DM, 0, 0, f1W, DM, 0, 0, f1B, ff, DI, 0, 0, MR, DI, DM, 1, 0);

        // tmp = ff @ ff2_w^T + b
        gemm_tf32<<<dim3(4, 32, 1), 256>>>(
            ff, DI, 0, 0, f2W, DI, 0, 0, f2B, tmp, DM, 0, 0, MR, DM, DI, 0, 0);

        add_ln<<<MR, 128>>>(h, tmp, ln2_s + l * DM, ln2_b + l * DM);
    }

    // cls = h @ cls_w^T + b
    gemm_tf32<<<dim3(1, 32, 1), 256>>>(
        h, DM, 0, 0, cls_w, DM, 0, 0, cls_b, cls, NCLS, 0, 0, MR, NCLS, DM, 0, 0);

    transpose_cls<<<dim3(TTT / 32, NCLS / 32, BB), dim3(32, 8)>>>(cls, outp);
}

// round 3
// speedup vs baseline: 1.7012x; 1.0789x over previous
#include <cuda_runtime.h>

// ---------------- problem constants ----------------
#define BB   2
#define TTT  2048
#define DM   512
#define NHD  8
#define DHD  64
#define NLAY 4
#define DI   2048
#define CIN  2048
#define NCLS 64
#define MR   (BB * TTT)   // 4096 token rows

// ---------------- scratch (device globals; no allocation allowed) ----------------
__device__ float g_xT[(size_t)BB * TTT * CIN];
__device__ float g_h[(size_t)MR * DM];
__device__ float g_tmp[(size_t)MR * DM];
__device__ float g_heads[(size_t)MR * 3 * DM];
__device__ float g_qw[(size_t)MR * DM];
__device__ float g_qr[(size_t)MR * DM];
__device__ float g_rk[(size_t)TTT * DM];
__device__ float g_pos[(size_t)TTT * DM];
__device__ float g_ff[(size_t)MR * DI];
__device__ float g_Bx[(size_t)BB * NHD * TTT * TTT];   // qr @ rk^T (unshifted)
__device__ float g_av[(size_t)MR * DM];
__device__ float g_cls[(size_t)MR * NCLS];

// ---------------- tf32 helpers ----------------
__device__ __forceinline__ unsigned f2tf(float x) {
    unsigned u;
    asm("cvt.rna.tf32.f32 %0, %1;" : "=r"(u) : "f"(x));
    return u;
}

__device__ __forceinline__ void mma_tf32(float* c, const unsigned* a, const unsigned* b) {
    asm volatile(
        "mma.sync.aligned.m16n8k8.row.col.f32.tf32.tf32.f32 "
        "{%0,%1,%2,%3}, {%4,%5,%6,%7}, {%8,%9}, {%0,%1,%2,%3};"
        : "+f"(c[0]), "+f"(c[1]), "+f"(c[2]), "+f"(c[3])
        : "r"(a[0]), "r"(a[1]), "r"(a[2]), "r"(a[3]), "r"(b[0]), "r"(b[1]));
}

// ---------------- TF32 tensor-core GEMM (dense layers) ----------------
__global__ void __launch_bounds__(256) gemm_tf32(
    const float* __restrict__ A, int lda, size_t sAb, size_t sAn,
    const float* __restrict__ B, int ldb, size_t sBb, size_t sBn,
    const float* __restrict__ bias,
    float* __restrict__ C, int ldc, size_t sCb, size_t sCn,
    int M, int N, int K, int relu, int bTrans)
{
    const int z = blockIdx.z, zb = z >> 3, zn = z & 7;
    A += (size_t)zb * sAb + (size_t)zn * sAn;
    B += (size_t)zb * sBb + (size_t)zn * sBn;
    C += (size_t)zb * sCb + (size_t)zn * sCn;

    __shared__ unsigned As[128][36];
    __shared__ unsigned Bs[128][36];

    const int tid = threadIdx.x;
    const int warp = tid >> 5, lane = tid & 31;
    const int wm = warp >> 2, wn = warp & 3;
    const int g = lane >> 2, tg = lane & 3;
    const int m0 = blockIdx.y * 128, n0 = blockIdx.x * 128;

    float acc[4][4][4];
#pragma unroll
    for (int mt = 0; mt < 4; mt++)
#pragma unroll
        for (int nt = 0; nt < 4; nt++)
#pragma unroll
            for (int i = 0; i < 4; i++) acc[mt][nt][i] = 0.f;

    for (int k0 = 0; k0 < K; k0 += 32) {
#pragma unroll
        for (int i = 0; i < 4; i++) {
            int idx = tid + i * 256;
            int row = idx >> 3;
            int kq = (idx & 7) * 4;
            float4 v = *(const float4*)(A + (size_t)(m0 + row) * lda + k0 + kq);
            As[row][kq + 0] = f2tf(v.x);
            As[row][kq + 1] = f2tf(v.y);
            As[row][kq + 2] = f2tf(v.z);
            As[row][kq + 3] = f2tf(v.w);
        }
        if (!bTrans) {
#pragma unroll
            for (int i = 0; i < 4; i++) {
                int idx = tid + i * 256;
                int row = idx >> 3;
                int kq = (idx & 7) * 4;
                float4 v = make_float4(0.f, 0.f, 0.f, 0.f);
                if (n0 + row < N) v = *(const float4*)(B + (size_t)(n0 + row) * ldb + k0 + kq);
                Bs[row][kq + 0] = f2tf(v.x);
                Bs[row][kq + 1] = f2tf(v.y);
                Bs[row][kq + 2] = f2tf(v.z);
                Bs[row][kq + 3] = f2tf(v.w);
            }
        } else {
#pragma unroll
            for (int i = 0; i < 16; i++) {
                int idx = tid + i * 256;
                int kk = idx >> 7, nn = idx & 127;
                float v = 0.f;
                if (n0 + nn < N) v = B[(size_t)(k0 + kk) * ldb + n0 + nn];
                Bs[nn][kk] = f2tf(v);
            }
        }
        __syncthreads();

#pragma unroll
        for (int ks = 0; ks < 4; ks++) {
            const int kk = ks * 8;
            unsigned a[4][4], bb[4][2];
#pragma unroll
            for (int mt = 0; mt < 4; mt++) {
                int r = wm * 64 + mt * 16;
                a[mt][0] = As[r + g][kk + tg];
                a[mt][1] = As[r + g + 8][kk + tg];
                a[mt][2] = As[r + g][kk + tg + 4];
                a[mt][3] = As[r + g + 8][kk + tg + 4];
            }
#pragma unroll
            for (int nt = 0; nt < 4; nt++) {
                int c = wn * 32 + nt * 8;
                bb[nt][0] = Bs[c + g][kk + tg];
                bb[nt][1] = Bs[c + g][kk + tg + 4];
            }
#pragma unroll
            for (int mt = 0; mt < 4; mt++)
#pragma unroll
                for (int nt = 0; nt < 4; nt++)
                    mma_tf32(acc[mt][nt], a[mt], bb[nt]);
        }
        __syncthreads();
    }

#pragma unroll
    for (int mt = 0; mt < 4; mt++) {
        int r0 = m0 + wm * 64 + mt * 16 + g;
#pragma unroll
        for (int nt = 0; nt < 4; nt++) {
            int c0 = n0 + wn * 32 + nt * 8 + tg * 2;
            if (c0 < N) {
                float b0v = bias ? bias[c0] : 0.f;
                float b1v = bias ? bias[c0 + 1] : 0.f;
                float v0 = acc[mt][nt][0] + b0v;
                float v1 = acc[mt][nt][1] + b1v;
                float v2 = acc[mt][nt][2] + b0v;
                float v3 = acc[mt][nt][3] + b1v;
                if (relu) {
                    v0 = fmaxf(v0, 0.f); v1 = fmaxf(v1, 0.f);
                    v2 = fmaxf(v2, 0.f); v3 = fmaxf(v3, 0.f);
                }
                *(float2*)(C + (size_t)r0 * ldc + c0) = make_float2(v0, v1);
                *(float2*)(C + (size_t)(r0 + 8) * ldc + c0) = make_float2(v2, v3);
            }
        }
    }
}

// ---------------- fused flash attention with rel-shift gather ----------------
// rel_shift(Bx)[i,j] = Bx[i, T-1-i+j] (j<=i) ; 0 (j==i+1) ; Bx[i+1, j-i-2] (j>i+1)
__device__ __forceinline__ float bdval(const float* __restrict__ Bb, int i, int j) {
    if (j <= i)      return Bb[(size_t)i * TTT + (TTT - 1 - i + j)];
    if (j == i + 1)  return 0.f;
    return Bb[(size_t)(i + 1) * TTT + (j - i - 2)];
}

#define FA_SMEM (2 * 128 * 65 * 4)

__global__ void __launch_bounds__(256, 1) flash_attn(
    const float* __restrict__ qw,     // [MR][512]
    const float* __restrict__ heads,  // [MR][1536]; K at +512, V at +1024
    const float* __restrict__ Bx,     // [16][T][T]
    float* __restrict__ av,           // [MR][512]
    float scale)
{
    extern __shared__ unsigned smem[];
    unsigned* sKV = smem;              // [128][65]: K rows 0-63, V^T rows 64-127
    unsigned* sP  = smem + 128 * 65;   // [128][65]: Q staging, then P (warp-private rows)

    const int tid = threadIdx.x;
    const int w = tid >> 5, lane = tid & 31;
    const int g = lane >> 2, tg = lane & 3;
    const int i0 = blockIdx.x * 128;
    const int bn = blockIdx.y;
    const int b = bn >> 3, n = bn & 7;

    const float* Qb = qw + ((size_t)b * TTT) * DM + n * 64;
    const float* Kb = heads + DM + ((size_t)b * TTT) * (3 * DM) + n * 64;
    const float* Vb = heads + 2 * DM + ((size_t)b * TTT) * (3 * DM) + n * 64;
    const float* Bb = Bx + (size_t)bn * TTT * TTT;

    // ---- stage Q tile [128][64] and extract per-warp A fragments
#pragma unroll
    for (int it = 0; it < 8; it++) {
        int idx = tid + it * 256;           // 2048 float4 slots
        int row = idx >> 4, c4 = (idx & 15) * 4;
        float4 v = *(const float4*)(Qb + (size_t)(i0 + row) * DM + c4);
        sP[row * 65 + c4 + 0] = f2tf(v.x);
        sP[row * 65 + c4 + 1] = f2tf(v.y);
        sP[row * 65 + c4 + 2] = f2tf(v.z);
        sP[row * 65 + c4 + 3] = f2tf(v.w);
    }
    __syncthreads();

    const int r0 = 16 * w + g;       // local row (this lane's first row)
    const int iR0 = i0 + r0, iR1 = iR0 + 8;

    unsigned qa[8][4];
#pragma unroll
    for (int kf = 0; kf < 8; kf++) {
        qa[kf][0] = sP[r0 * 65 + kf * 8 + tg];
        qa[kf][1] = sP[(r0 + 8) * 65 + kf * 8 + tg];
        qa[kf][2] = sP[r0 * 65 + kf * 8 + tg + 4];
        qa[kf][3] = sP[(r0 + 8) * 65 + kf * 8 + tg + 4];
    }

    float Oacc[8][4];
#pragma unroll
    for (int nf = 0; nf < 8; nf++)
#pragma unroll
        for (int i = 0; i < 4; i++) Oacc[nf][i] = 0.f;
    float mr0 = -1e30f, mr1 = -1e30f, lr0 = 0.f, lr1 = 0.f;

    for (int j0 = 0; j0 < TTT; j0 += 64) {
        __syncthreads();   // previous iteration's MMAs done with sKV/sP
        // ---- load K tile [64 j][64 d]
#pragma unroll
        for (int it = 0; it < 4; it++) {
            int idx = tid + it * 256;       // 1024 float4 slots
            int row = idx >> 4, c4 = (idx & 15) * 4;
            float4 v = *(const float4*)(Kb + (size_t)(j0 + row) * (3 * DM) + c4);
            sKV[row * 65 + c4 + 0] = f2tf(v.x);
            sKV[row * 65 + c4 + 1] = f2tf(v.y);
            sKV[row * 65 + c4 + 2] = f2tf(v.z);
            sKV[row * 65 + c4 + 3] = f2tf(v.w);
        }
        // ---- load V tile transposed: Vt[d][j]
#pragma unroll
        for (int it = 0; it < 4; it++) {
            int idx = tid + it * 256;
            int j = idx >> 4, d4 = (idx & 15) * 4;
            float4 v = *(const float4*)(Vb + (size_t)(j0 + j) * (3 * DM) + d4);
            sKV[(64 + d4 + 0) * 65 + j] = f2tf(v.x);
            sKV[(64 + d4 + 1) * 65 + j] = f2tf(v.y);
            sKV[(64 + d4 + 2) * 65 + j] = f2tf(v.z);
            sKV[(64 + d4 + 3) * 65 + j] = f2tf(v.w);
        }
        __syncthreads();

        // ---- S = Q @ K^T  (warp computes 16 rows x 64 cols)
        float s[8][4];
#pragma unroll
        for (int nf = 0; nf < 8; nf++)
#pragma unroll
            for (int i = 0; i < 4; i++) s[nf][i] = 0.f;
#pragma unroll
        for (int kf = 0; kf < 8; kf++) {
#pragma unroll
            for (int nf = 0; nf < 8; nf++) {
                unsigned bb[2];
                bb[0] = sKV[(nf * 8 + g) * 65 + kf * 8 + tg];
                bb[1] = sKV[(nf * 8 + g) * 65 + kf * 8 + tg + 4];
                mma_tf32(s[nf], qa[kf], bb);
            }
        }

        // ---- add shifted BD, scale
#pragma unroll
        for (int nf = 0; nf < 8; nf++) {
            int j = j0 + nf * 8 + 2 * tg;
            s[nf][0] = (s[nf][0] + bdval(Bb, iR0, j))     * scale;
            s[nf][1] = (s[nf][1] + bdval(Bb, iR0, j + 1)) * scale;
            s[nf][2] = (s[nf][2] + bdval(Bb, iR1, j))     * scale;
            s[nf][3] = (s[nf][3] + bdval(Bb, iR1, j + 1)) * scale;
        }

        // ---- online softmax (rows iR0, iR1 owned by this quad)
        float m0 = -1e30f, m1 = -1e30f;
#pragma unroll
        for (int nf = 0; nf < 8; nf++) {
            m0 = fmaxf(m0, fmaxf(s[nf][0], s[nf][1]));
            m1 = fmaxf(m1, fmaxf(s[nf][2], s[nf][3]));
        }
        m0 = fmaxf(m0, __shfl_xor_sync(0xffffffffu, m0, 1));
        m0 = fmaxf(m0, __shfl_xor_sync(0xffffffffu, m0, 2));
        m1 = fmaxf(m1, __shfl_xor_sync(0xffffffffu, m1, 1));
        m1 = fmaxf(m1, __shfl_xor_sync(0xffffffffu, m1, 2));
        float mn0 = fmaxf(mr0, m0), mn1 = fmaxf(mr1, m1);
        float a0 = __expf(mr0 - mn0), a1 = __expf(mr1 - mn1);

        float l0 = 0.f, l1 = 0.f;
#pragma unroll
        for (int nf = 0; nf < 8; nf++) {
            float p0 = __expf(s[nf][0] - mn0);
            float p1 = __expf(s[nf][1] - mn0);
            float p2 = __expf(s[nf][2] - mn1);
            float p3 = __expf(s[nf][3] - mn1);
            l0 += p0 + p1; l1 += p2 + p3;
            int c = nf * 8 + 2 * tg;
            sP[r0 * 65 + c]           = f2tf(p0);
            sP[r0 * 65 + c + 1]       = f2tf(p1);
            sP[(r0 + 8) * 65 + c]     = f2tf(p2);
            sP[(r0 + 8) * 65 + c + 1] = f2tf(p3);
        }
        l0 += __shfl_xor_sync(0xffffffffu, l0, 1);
        l0 += __shfl_xor_sync(0xffffffffu, l0, 2);
        l1 += __shfl_xor_sync(0xffffffffu, l1, 1);
        l1 += __shfl_xor_sync(0xffffffffu, l1, 2);
        lr0 = lr0 * a0 + l0;
        lr1 = lr1 * a1 + l1;
        mr0 = mn0; mr1 = mn1;
#pragma unroll
        for (int nf = 0; nf < 8; nf++) {
            Oacc[nf][0] *= a0; Oacc[nf][1] *= a0;
            Oacc[nf][2] *= a1; Oacc[nf][3] *= a1;
        }
        __syncwarp();

        // ---- O += P @ V   (A frags from sP, B frags from Vt)
#pragma unroll
        for (int kf = 0; kf < 8; kf++) {
            unsigned pa[4];
            pa[0] = sP[r0 * 65 + kf * 8 + tg];
            pa[1] = sP[(r0 + 8) * 65 + kf * 8 + tg];
            pa[2] = sP[r0 * 65 + kf * 8 + tg + 4];
            pa[3] = sP[(r0 + 8) * 65 + kf * 8 + tg + 4];
#pragma unroll
            for (int nf = 0; nf < 8; nf++) {
                unsigned bb[2];
                bb[0] = sKV[(64 + nf * 8 + g) * 65 + kf * 8 + tg];
                bb[1] = sKV[(64 + nf * 8 + g) * 65 + kf * 8 + tg + 4];
                mma_tf32(Oacc[nf], pa, bb);
            }
        }
    }

    // ---- finalize and write av
    float inv0 = 1.f / lr0, inv1 = 1.f / lr1;
#pragma unroll
    for (int nf = 0; nf < 8; nf++) {
        int col = n * 64 + nf * 8 + 2 * tg;
        *(float2*)(av + (size_t)(b * TTT + iR0) * DM + col) =
            make_float2(Oacc[nf][0] * inv0, Oacc[nf][1] * inv0);
        *(float2*)(av + (size_t)(b * TTT + iR1) * DM + col) =
            make_float2(Oacc[nf][2] * inv1, Oacc[nf][3] * inv1);
    }
}

// ---------------- residual add + LayerNorm over d=512 ----------------
__global__ void __launch_bounds__(128) add_ln(
    float* __restrict__ h, const float* __restrict__ a,
    const float* __restrict__ gs, const float* __restrict__ gb)
{
    const int row = blockIdx.x, tid = threadIdx.x;
    float* hp = h + (size_t)row * DM;
    const float* ap = a + (size_t)row * DM;
    float v[4];
    float s = 0.f;
#pragma unroll
    for (int j = 0; j < 4; j++) { int c = tid + j * 128; v[j] = hp[c] + ap[c]; s += v[j]; }

    __shared__ float red[8];
#pragma unroll
    for (int o = 16; o > 0; o >>= 1) s += __shfl_xor_sync(0xffffffffu, s, o);
    if ((tid & 31) == 0) red[tid >> 5] = s;
    __syncthreads();
    float mean = (red[0] + red[1] + red[2] + red[3]) * (1.f / 512.f);

    float var = 0.f;
#pragma unroll
    for (int j = 0; j < 4; j++) { float d = v[j] - mean; var += d * d; }
#pragma unroll
    for (int o = 16; o > 0; o >>= 1) var += __shfl_xor_sync(0xffffffffu, var, o);
    if ((tid & 31) == 0) red[4 + (tid >> 5)] = var;
    __syncthreads();
    var = (red[4] + red[5] + red[6] + red[7]) * (1.f / 512.f);
    float rs = rsqrtf(var + 1e-5f);
#pragma unroll
    for (int j = 0; j < 4; j++) {
        int c = tid + j * 128;
        hp[c] = (v[j] - mean) * rs * gs[c] + gb[c];
    }
}

// ---------------- small helpers ----------------
__global__ void __launch_bounds__(256) make_qwr(
    const float* __restrict__ heads, const float* __restrict__ rw,
    const float* __restrict__ rr, float* __restrict__ qw, float* __restrict__ qr)
{
    int idx = blockIdx.x * 256 + threadIdx.x;
    int m = idx >> 9, c = idx & 511;
    float q = heads[(size_t)m * 1536 + c];
    qw[idx] = q + rw[c];
    qr[idx] = q + rr[c];
}

__global__ void __launch_bounds__(256) pos_kernel(float* __restrict__ pos)
{
    int p = blockIdx.x;
    int f = threadIdx.x;
    float ps = (float)(TTT - 1 - p);
    float invf = 1.0f / powf(10000.0f, (float)(2 * f) / (float)DM);
    float ang = ps * invf;
    pos[(size_t)p * DM + f]       = sinf(ang);
    pos[(size_t)p * DM + 256 + f] = cosf(ang);
}

__global__ void transpose_x(const float* __restrict__ x, float* __restrict__ xT)
{
    __shared__ float tile[32][33];
    int b = blockIdx.z;
    int t0 = blockIdx.x * 32, c0 = blockIdx.y * 32;
    int tx = threadIdx.x, ty = threadIdx.y;
#pragma unroll
    for (int i = 0; i < 4; i++) {
        int c = c0 + ty + i * 8;
        tile[ty + i * 8][tx] = x[((size_t)b * CIN + c) * TTT + t0 + tx];
    }
    __syncthreads();
#pragma unroll
    for (int i = 0; i < 4; i++) {
        int t = t0 + ty + i * 8;
        xT[((size_t)b * TTT + t) * CIN + c0 + tx] = tile[tx][ty + i * 8];
    }
}

__global__ void transpose_cls(const float* __restrict__ tmp, float* __restrict__ outp)
{
    __shared__ float tile[32][33];
    int b = blockIdx.z;
    int t0 = blockIdx.x * 32, k0 = blockIdx.y * 32;
    int tx = threadIdx.x, ty = threadIdx.y;
#pragma unroll
    for (int i = 0; i < 4; i++) {
        int t = t0 + ty + i * 8;
        tile[ty + i * 8][tx] = tmp[((size_t)b * TTT + t) * NCLS + k0 + tx];
    }
    __syncthreads();
#pragma unroll
    for (int i = 0; i < 4; i++) {
        int k = k0 + ty + i * 8;
        outp[((size_t)b * NCLS + k) * TTT + t0 + tx] = tile[tx][ty + i * 8];
    }
}

// ---------------- host orchestration ----------------
extern "C" void kernel_launch(void* const* d_in, const int* in_sizes, int n_in,
                              void* d_out, int out_size)
{
    const float* x        = (const float*)d_in[0];
    const float* emb_w    = (const float*)d_in[1];
    const float* emb_b    = (const float*)d_in[2];
    const float* r_w_bias = (const float*)d_in[3];
    const float* r_r_bias = (const float*)d_in[4];
    const float* qkv_w    = (const float*)d_in[5];
    const float* qkv_b    = (const float*)d_in[6];
    const float* r_proj_w = (const float*)d_in[7];
    const float* o_w      = (const float*)d_in[8];
    const float* ln1_s    = (const float*)d_in[9];
    const float* ln1_b    = (const float*)d_in[10];
    const float* ff1_w    = (const float*)d_in[11];
    const float* ff1_b    = (const float*)d_in[12];
    const float* ff2_w    = (const float*)d_in[13];
    const float* ff2_b    = (const float*)d_in[14];
    const float* ln2_s    = (const float*)d_in[15];
    const float* ln2_b    = (const float*)d_in[16];
    const float* cls_w    = (const float*)d_in[17];
    const float* cls_b    = (const float*)d_in[18];
    float* outp = (float*)d_out;

    float *xT, *h, *tmp, *heads, *qw, *qr, *rk, *pos, *ff, *Bx, *av, *cls;
    cudaGetSymbolAddress((void**)&xT, g_xT);
    cudaGetSymbolAddress((void**)&h, g_h);
    cudaGetSymbolAddress((void**)&tmp, g_tmp);
    cudaGetSymbolAddress((void**)&heads, g_heads);
    cudaGetSymbolAddress((void**)&qw, g_qw);
    cudaGetSymbolAddress((void**)&qr, g_qr);
    cudaGetSymbolAddress((void**)&rk, g_rk);
    cudaGetSymbolAddress((void**)&pos, g_pos);
    cudaGetSymbolAddress((void**)&ff, g_ff);
    cudaGetSymbolAddress((void**)&Bx, g_Bx);
    cudaGetSymbolAddress((void**)&av, g_av);
    cudaGetSymbolAddress((void**)&cls, g_cls);

    cudaFuncSetAttribute(flash_attn, cudaFuncAttributeMaxDynamicSharedMemorySize, FA_SMEM);

    const float scale = 1.0f / 8.0f;

    transpose_x<<<dim3(TTT / 32, CIN / 32, BB), dim3(32, 8)>>>(x, xT);
    pos_kernel<<<TTT, 256>>>(pos);

    // embed: h = xT @ emb_w^T + emb_b
    gemm_tf32<<<dim3(4, 32, 1), 256>>>(
        xT, CIN, 0, 0, emb_w, CIN, 0, 0, emb_b, h, DM, 0, 0, MR, DM, CIN, 0, 0);

    for (int l = 0; l < NLAY; l++) {
        const float* qkvW = qkv_w + (size_t)l * 3 * DM * DM;
        const float* qkvB = qkv_b + (size_t)l * 3 * DM;
        const float* rW   = r_proj_w + (size_t)l * DM * DM;
        const float* oW   = o_w + (size_t)l * DM * DM;
        const float* f1W  = ff1_w + (size_t)l * DI * DM;
        const float* f1B  = ff1_b + (size_t)l * DI;
        const float* f2W  = ff2_w + (size_t)l * DM * DI;
        const float* f2B  = ff2_b + (size_t)l * DM;

        // heads = h @ qkv_w^T + b
        gemm_tf32<<<dim3(12, 32, 1), 256>>>(
            h, DM, 0, 0, qkvW, DM, 0, 0, qkvB, heads, 3 * DM, 0, 0, MR, 3 * DM, DM, 0, 0);

        make_qwr<<<(MR * DM) / 256, 256>>>(heads, r_w_bias, r_r_bias, qw, qr);

        // rk = pos @ r_proj_w^T
        gemm_tf32<<<dim3(4, 16, 1), 256>>>(
            pos, DM, 0, 0, rW, DM, 0, 0, nullptr, rk, DM, 0, 0, TTT, DM, DM, 0, 0);

        // Bx[b,n] = qr @ rk_n^T  (unshifted position scores)
        gemm_tf32<<<dim3(16, 16, BB * NHD), 256>>>(
            qr, DM, (size_t)TTT * DM, 64,
            rk, DM, 0, 64,
            nullptr,
            Bx, TTT, (size_t)NHD * TTT * TTT, (size_t)TTT * TTT,
            TTT, TTT, 64, 0, 0);

        // fused: av = softmax((qw K^T + shift(Bx)) * scale) @ V
        flash_attn<<<dim3(TTT / 128, BB * NHD), 256, FA_SMEM>>>(qw, heads, Bx, av, scale);

        // attn_out = av @ o_w^T
        gemm_tf32<<<dim3(4, 32, 1), 256>>>(
            av, DM, 0, 0, oW, DM, 0, 0, nullptr, tmp, DM, 0, 0, MR, DM, DM, 0, 0);

        add_ln<<<MR, 128>>>(h, tmp, ln1_s + l * DM, ln1_b + l * DM);

        // ff = relu(h @ ff1_w^T + b)
        gemm_tf32<<<dim3(16, 32, 1), 256>>>(
            h, DM, 0, 0, f1W, DM, 0, 0, f1B, ff, DI, 0, 0, MR, DI, DM, 1, 0);

        // tmp = ff @ ff2_w^T + b
        gemm_tf32<<<dim3(4, 32, 1), 256>>>(
            ff, DI, 0, 0, f2W, DI, 0, 0, f2B, tmp, DM, 0, 0, MR, DM, DI, 0, 0);

        add_ln<<<MR, 128>>>(h, tmp, ln2_s + l * DM, ln2_b + l * DM);
    }

    // cls = h @ cls_w^T + b
    gemm_tf32<<<dim3(1, 32, 1), 256>>>(
        h, DM, 0, 0, cls_w, DM, 0, 0, cls_b, cls, NCLS, 0, 0, MR, NCLS, DM, 0, 0);

    transpose_cls<<<dim3(TTT / 32, NCLS / 32, BB), dim3(32, 8)>>>(cls, outp);
}

// round 5
// speedup vs baseline: 2.3302x; 1.3697x over previous
#include <cuda_runtime.h>

// ---------------- problem constants ----------------
#define BB   2
#define TTT  2048
#define DM   512
#define NHD  8
#define DHD  64
#define NLAY 4
#define DI   2048
#define CIN  2048
#define NCLS 64
#define MR   (BB * TTT)   // 4096 token rows

// ---------------- scratch (device globals; no allocation allowed) ----------------
__device__ float g_xT[(size_t)BB * TTT * CIN];
__device__ float g_h[(size_t)MR * DM];
__device__ float g_tmp[(size_t)MR * DM];
__device__ float g_heads[(size_t)MR * 3 * DM];
__device__ float g_qw[(size_t)MR * DM];
__device__ float g_qr[(size_t)MR * DM];
__device__ float g_rk[(size_t)TTT * DM];
__device__ float g_pos[(size_t)TTT * DM];
__device__ float g_ff[(size_t)MR * DI];
__device__ float g_Bx[(size_t)BB * NHD * TTT * TTT];   // qr @ rk^T (unshifted)
__device__ float g_av[(size_t)MR * DM];
__device__ float g_cls[(size_t)MR * NCLS];

// ---------------- tf32 / cp.async helpers ----------------
__device__ __forceinline__ unsigned f2tf(float x) {
    unsigned u;
    asm("cvt.rna.tf32.f32 %0, %1;" : "=r"(u) : "f"(x));
    return u;
}

__device__ __forceinline__ void mma_tf32(float* c, const unsigned* a, const unsigned* b) {
    asm volatile(
        "mma.sync.aligned.m16n8k8.row.col.f32.tf32.tf32.f32 "
        "{%0,%1,%2,%3}, {%4,%5,%6,%7}, {%8,%9}, {%0,%1,%2,%3};"
        : "+f"(c[0]), "+f"(c[1]), "+f"(c[2]), "+f"(c[3])
        : "r"(a[0]), "r"(a[1]), "r"(a[2]), "r"(a[3]), "r"(b[0]), "r"(b[1]));
}

__device__ __forceinline__ void cp16(void* dst, const void* src, int srcbytes) {
    unsigned u = (unsigned)__cvta_generic_to_shared(dst);
    asm volatile("cp.async.cg.shared.global [%0], [%1], 16, %2;"
                 :: "r"(u), "l"(src), "r"(srcbytes));
}
__device__ __forceinline__ void cp_commit() {
    asm volatile("cp.async.commit_group;");
}

// ---------------- TF32 tensor-core GEMM, 2-stage cp.async pipeline ----------------
// C[M,N] = A[M,K] @ B^T (+bias)(+relu). A[m][k], B[n][k] row-major.
// M % 128 == 0, K % 32 == 0. N predicated.
#define GSM_STAGE (128 * 36)
#define GEMM_SMEM (4 * GSM_STAGE * 4)   // 2 stages x (A+B) x 128x36 floats = 73728 B

__global__ void __launch_bounds__(256) gemm_tf32(
    const float* __restrict__ A, int lda, size_t sAb, size_t sAn,
    const float* __restrict__ B, int ldb, size_t sBb, size_t sBn,
    const float* __restrict__ bias,
    float* __restrict__ C, int ldc, size_t sCb, size_t sCn,
    int M, int N, int K, int relu)
{
    const int z = blockIdx.z, zb = z >> 3, zn = z & 7;
    A += (size_t)zb * sAb + (size_t)zn * sAn;
    B += (size_t)zb * sBb + (size_t)zn * sBn;
    C += (size_t)zb * sCb + (size_t)zn * sCn;

    extern __shared__ float gsm[];
    float* AsBase = gsm;                  // [2][128*36]
    float* BsBase = gsm + 2 * GSM_STAGE;  // [2][128*36]

    const int tid = threadIdx.x;
    const int warp = tid >> 5, lane = tid & 31;
    const int wm = warp >> 2, wn = warp & 3;
    const int g = lane >> 2, tg = lane & 3;
    const int m0 = blockIdx.y * 128, n0 = blockIdx.x * 128;

    float acc[4][4][4];
#pragma unroll
    for (int mt = 0; mt < 4; mt++)
#pragma unroll
        for (int nt = 0; nt < 4; nt++)
#pragma unroll
            for (int i = 0; i < 4; i++) acc[mt][nt][i] = 0.f;

    const int KT = K >> 5;

    auto load_stage = [&](int st, int k0) {
#pragma unroll
        for (int i = 0; i < 4; i++) {
            int idx = tid + i * 256;
            int row = idx >> 3;
            int kq = (idx & 7) * 4;
            cp16(&AsBase[st * GSM_STAGE + row * 36 + kq],
                 A + (size_t)(m0 + row) * lda + k0 + kq, 16);
        }
#pragma unroll
        for (int i = 0; i < 4; i++) {
            int idx = tid + i * 256;
            int row = idx >> 3;
            int kq = (idx & 7) * 4;
            int ok = (n0 + row) < N;
            cp16(&BsBase[st * GSM_STAGE + row * 36 + kq],
                 B + (size_t)(ok ? (n0 + row) : 0) * ldb + k0 + kq, ok ? 16 : 0);
        }
        cp_commit();
    };

    load_stage(0, 0);

    for (int kt = 0; kt < KT; kt++) {
        const int st = kt & 1;
        if (kt + 1 < KT) {
            load_stage(st ^ 1, (kt + 1) * 32);
            asm volatile("cp.async.wait_group 1;");
        } else {
            asm volatile("cp.async.wait_group 0;");
        }
        __syncthreads();

        const float* Asl = AsBase + st * GSM_STAGE;
        const float* Bsl = BsBase + st * GSM_STAGE;

#pragma unroll
        for (int ks = 0; ks < 4; ks++) {
            const int kk = ks * 8;
            unsigned a[4][4], bb[4][2];
#pragma unroll
            for (int mt = 0; mt < 4; mt++) {
                int r = wm * 64 + mt * 16;
                a[mt][0] = f2tf(Asl[(r + g) * 36 + kk + tg]);
                a[mt][1] = f2tf(Asl[(r + g + 8) * 36 + kk + tg]);
                a[mt][2] = f2tf(Asl[(r + g) * 36 + kk + tg + 4]);
                a[mt][3] = f2tf(Asl[(r + g + 8) * 36 + kk + tg + 4]);
            }
#pragma unroll
            for (int nt = 0; nt < 4; nt++) {
                int c = wn * 32 + nt * 8;
                bb[nt][0] = f2tf(Bsl[(c + g) * 36 + kk + tg]);
                bb[nt][1] = f2tf(Bsl[(c + g) * 36 + kk + tg + 4]);
            }
#pragma unroll
            for (int mt = 0; mt < 4; mt++)
#pragma unroll
                for (int nt = 0; nt < 4; nt++)
                    mma_tf32(acc[mt][nt], a[mt], bb[nt]);
        }
        __syncthreads();
    }

#pragma unroll
    for (int mt = 0; mt < 4; mt++) {
        int r0 = m0 + wm * 64 + mt * 16 + g;
#pragma unroll
        for (int nt = 0; nt < 4; nt++) {
            int c0 = n0 + wn * 32 + nt * 8 + tg * 2;
            if (c0 < N) {
                float b0v = bias ? bias[c0] : 0.f;
                float b1v = bias ? bias[c0 + 1] : 0.f;
                float v0 = acc[mt][nt][0] + b0v;
                float v1 = acc[mt][nt][1] + b1v;
                float v2 = acc[mt][nt][2] + b0v;
                float v3 = acc[mt][nt][3] + b1v;
                if (relu) {
                    v0 = fmaxf(v0, 0.f); v1 = fmaxf(v1, 0.f);
                    v2 = fmaxf(v2, 0.f); v3 = fmaxf(v3, 0.f);
                }
                *(float2*)(C + (size_t)r0 * ldc + c0) = make_float2(v0, v1);
                *(float2*)(C + (size_t)(r0 + 8) * ldc + c0) = make_float2(v2, v3);
            }
        }
    }
}

// ---------------- fused flash attention with rel-shift gather ----------------
// rel_shift(Bx)[i,j] = Bx[i, T-1-i+j] (j<=i) ; 0 (j==i+1) ; Bx[i+1, j-i-2] (j>i+1)
__device__ __forceinline__ float bdval(const float* __restrict__ Bb, int i, int j) {
    if (j <= i)      return Bb[(size_t)i * TTT + (TTT - 1 - i + j)];
    if (j == i + 1)  return 0.f;
    return Bb[(size_t)(i + 1) * TTT + (j - i - 2)];
}

// smem: sP (tf32) [128][68] | sK (float) [2][64][68] | sV (float) [2][64][72]
#define SP_ELEMS (128 * 68)
#define SK_ELEMS (64 * 68)
#define SV_ELEMS (64 * 72)
#define FA_SMEM ((SP_ELEMS + 2 * SK_ELEMS + 2 * SV_ELEMS) * 4)

__global__ void __launch_bounds__(256, 1) flash_attn(
    const float* __restrict__ qw,     // [MR][512]
    const float* __restrict__ heads,  // [MR][1536]; K at +512, V at +1024
    const float* __restrict__ Bx,     // [16][T][T]
    float* __restrict__ av,           // [MR][512]
    float scale)
{
    extern __shared__ unsigned smem_u[];
    unsigned* sP = smem_u;                              // tf32 Q staging / P tile [128][68]
    float* sK = (float*)(smem_u + SP_ELEMS);            // [2][64][68]
    float* sV = (float*)(smem_u + SP_ELEMS) + 2 * SK_ELEMS;  // [2][64][72]

    const int tid = threadIdx.x;
    const int w = tid >> 5, lane = tid & 31;
    const int g = lane >> 2, tg = lane & 3;
    const int i0 = blockIdx.x * 128;
    const int bn = blockIdx.y;
    const int b = bn >> 3, n = bn & 7;

    const float* Qb = qw + ((size_t)b * TTT) * DM + n * 64;
    const float* Kb = heads + DM + ((size_t)b * TTT) * (3 * DM) + n * 64;
    const float* Vb = heads + 2 * DM + ((size_t)b * TTT) * (3 * DM) + n * 64;
    const float* Bb = Bx + (size_t)bn * TTT * TTT;

    auto kv_load = [&](int st, int j0) {
#pragma unroll
        for (int it = 0; it < 4; it++) {
            int idx = tid + it * 256;        // 1024 float4 slots
            int row = idx >> 4, c4 = (idx & 15) * 4;
            cp16(&sK[st * SK_ELEMS + row * 68 + c4],
                 Kb + (size_t)(j0 + row) * (3 * DM) + c4, 16);
        }
#pragma unroll
        for (int it = 0; it < 4; it++) {
            int idx = tid + it * 256;
            int row = idx >> 4, c4 = (idx & 15) * 4;
            cp16(&sV[st * SV_ELEMS + row * 72 + c4],
                 Vb + (size_t)(j0 + row) * (3 * DM) + c4, 16);
        }
        cp_commit();
    };

    // prefetch first KV tile, then stage Q
    kv_load(0, 0);

#pragma unroll
    for (int it = 0; it < 8; it++) {
        int idx = tid + it * 256;           // 2048 float4 slots
        int row = idx >> 4, c4 = (idx & 15) * 4;
        float4 v = *(const float4*)(Qb + (size_t)(i0 + row) * DM + c4);
        sP[row * 68 + c4 + 0] = f2tf(v.x);
        sP[row * 68 + c4 + 1] = f2tf(v.y);
        sP[row * 68 + c4 + 2] = f2tf(v.z);
        sP[row * 68 + c4 + 3] = f2tf(v.w);
    }
    __syncthreads();

    const int r0 = 16 * w + g;
    const int iR0 = i0 + r0, iR1 = iR0 + 8;

    unsigned qa[8][4];
#pragma unroll
    for (int kf = 0; kf < 8; kf++) {
        qa[kf][0] = sP[r0 * 68 + kf * 8 + tg];
        qa[kf][1] = sP[(r0 + 8) * 68 + kf * 8 + tg];
        qa[kf][2] = sP[r0 * 68 + kf * 8 + tg + 4];
        qa[kf][3] = sP[(r0 + 8) * 68 + kf * 8 + tg + 4];
    }

    float Oacc[8][4];
#pragma unroll
    for (int nf = 0; nf < 8; nf++)
#pragma unroll
        for (int i = 0; i < 4; i++) Oacc[nf][i] = 0.f;
    float mr0 = -1e30f, mr1 = -1e30f, lr0 = 0.f, lr1 = 0.f;

    for (int jt = 0; jt < TTT / 64; jt++) {
        const int st = jt & 1;
        const int j0 = jt * 64;
        if (jt + 1 < TTT / 64) {
            kv_load(st ^ 1, (jt + 1) * 64);
            asm volatile("cp.async.wait_group 1;");
        } else {
            asm volatile("cp.async.wait_group 0;");
        }
        __syncthreads();

        const float* Ks = sK + st * SK_ELEMS;
        const float* Vs = sV + st * SV_ELEMS;

        // ---- S = Q @ K^T
        float s[8][4];
#pragma unroll
        for (int nf = 0; nf < 8; nf++)
#pragma unroll
            for (int i = 0; i < 4; i++) s[nf][i] = 0.f;
#pragma unroll
        for (int kf = 0; kf < 8; kf++) {
            const int kk = kf * 8;
#pragma unroll
            for (int nf = 0; nf < 8; nf++) {
                unsigned bb[2];
                bb[0] = f2tf(Ks[(nf * 8 + g) * 68 + kk + tg]);
                bb[1] = f2tf(Ks[(nf * 8 + g) * 68 + kk + tg + 4]);
                mma_tf32(s[nf], qa[kf], bb);
            }
        }

        // ---- add shifted BD, scale
#pragma unroll
        for (int nf = 0; nf < 8; nf++) {
            int j = j0 + nf * 8 + 2 * tg;
            s[nf][0] = (s[nf][0] + bdval(Bb, iR0, j))     * scale;
            s[nf][1] = (s[nf][1] + bdval(Bb, iR0, j + 1)) * scale;
            s[nf][2] = (s[nf][2] + bdval(Bb, iR1, j))     * scale;
            s[nf][3] = (s[nf][3] + bdval(Bb, iR1, j + 1)) * scale;
        }

        // ---- online softmax
        float m0 = -1e30f, m1 = -1e30f;
#pragma unroll
        for (int nf = 0; nf < 8; nf++) {
            m0 = fmaxf(m0, fmaxf(s[nf][0], s[nf][1]));
            m1 = fmaxf(m1, fmaxf(s[nf][2], s[nf][3]));
        }
        m0 = fmaxf(m0, __shfl_xor_sync(0xffffffffu, m0, 1));
        m0 = fmaxf(m0, __shfl_xor_sync(0xffffffffu, m0, 2));
        m1 = fmaxf(m1, __shfl_xor_sync(0xffffffffu, m1, 1));
        m1 = fmaxf(m1, __shfl_xor_sync(0xffffffffu, m1, 2));
        float mn0 = fmaxf(mr0, m0), mn1 = fmaxf(mr1, m1);
        float a0 = __expf(mr0 - mn0), a1 = __expf(mr1 - mn1);

        float l0 = 0.f, l1 = 0.f;
#pragma unroll
        for (int nf = 0; nf < 8; nf++) {
            float p0 = __expf(s[nf][0] - mn0);
            float p1 = __expf(s[nf][1] - mn0);
            float p2 = __expf(s[nf][2] - mn1);
            float p3 = __expf(s[nf][3] - mn1);
            l0 += p0 + p1; l1 += p2 + p3;
            int c = nf * 8 + 2 * tg;
            sP[r0 * 68 + c]           = f2tf(p0);
            sP[r0 * 68 + c + 1]       = f2tf(p1);
            sP[(r0 + 8) * 68 + c]     = f2tf(p2);
            sP[(r0 + 8) * 68 + c + 1] = f2tf(p3);
        }
        l0 += __shfl_xor_sync(0xffffffffu, l0, 1);
        l0 += __shfl_xor_sync(0xffffffffu, l0, 2);
        l1 += __shfl_xor_sync(0xffffffffu, l1, 1);
        l1 += __shfl_xor_sync(0xffffffffu, l1, 2);
        lr0 = lr0 * a0 + l0;
        lr1 = lr1 * a1 + l1;
        mr0 = mn0; mr1 = mn1;
#pragma unroll
        for (int nf = 0; nf < 8; nf++) {
            Oacc[nf][0] *= a0; Oacc[nf][1] *= a0;
            Oacc[nf][2] *= a1; Oacc[nf][3] *= a1;
        }
        __syncwarp();

        // ---- O += P @ V   (A frags from sP, B frags from untransposed V)
#pragma unroll
        for (int kf = 0; kf < 8; kf++) {
            const int kk = kf * 8;
            unsigned pa[4];
            pa[0] = sP[r0 * 68 + kk + tg];
            pa[1] = sP[(r0 + 8) * 68 + kk + tg];
            pa[2] = sP[r0 * 68 + kk + tg + 4];
            pa[3] = sP[(r0 + 8) * 68 + kk + tg + 4];
#pragma unroll
            for (int nf = 0; nf < 8; nf++) {
                unsigned bb[2];
                bb[0] = f2tf(Vs[(kk + tg) * 72 + nf * 8 + g]);
                bb[1] = f2tf(Vs[(kk + tg + 4) * 72 + nf * 8 + g]);
                mma_tf32(Oacc[nf], pa, bb);
            }
        }
        __syncthreads();
    }

    // ---- finalize and write av
    float inv0 = 1.f / lr0, inv1 = 1.f / lr1;
#pragma unroll
    for (int nf = 0; nf < 8; nf++) {
        int col = n * 64 + nf * 8 + 2 * tg;
        *(float2*)(av + (size_t)(b * TTT + iR0) * DM + col) =
            make_float2(Oacc[nf][0] * inv0, Oacc[nf][1] * inv0);
        *(float2*)(av + (size_t)(b * TTT + iR1) * DM + col) =
            make_float2(Oacc[nf][2] * inv1, Oacc[nf][3] * inv1);
    }
}

// ---------------- residual add + LayerNorm over d=512 ----------------
__global__ void __launch_bounds__(128) add_ln(
    float* __restrict__ h, const float* __restrict__ a,
    const float* __restrict__ gs, const float* __restrict__ gb)
{
    const int row = blockIdx.x, tid = threadIdx.x;
    float* hp = h + (size_t)row * DM;
    const float* ap = a + (size_t)row * DM;
    float v[4];
    float s = 0.f;
#pragma unroll
    for (int j = 0; j < 4; j++) { int c = tid + j * 128; v[j] = hp[c] + ap[c]; s += v[j]; }

    __shared__ float red[8];
#pragma unroll
    for (int o = 16; o > 0; o >>= 1) s += __shfl_xor_sync(0xffffffffu, s, o);
    if ((tid & 31) == 0) red[tid >> 5] = s;
    __syncthreads();
    float mean = (red[0] + red[1] + red[2] + red[3]) * (1.f / 512.f);

    float var = 0.f;
#pragma unroll
    for (int j = 0; j < 4; j++) { float d = v[j] - mean; var += d * d; }
#pragma unroll
    for (int o = 16; o > 0; o >>= 1) var += __shfl_xor_sync(0xffffffffu, var, o);
    if ((tid & 31) == 0) red[4 + (tid >> 5)] = var;
    __syncthreads();
    var = (red[4] + red[5] + red[6] + red[7]) * (1.f / 512.f);
    float rs = rsqrtf(var + 1e-5f);
#pragma unroll
    for (int j = 0; j < 4; j++) {
        int c = tid + j * 128;
        hp[c] = (v[j] - mean) * rs * gs[c] + gb[c];
    }
}

// ---------------- small helpers ----------------
__global__ void __launch_bounds__(256) make_qwr(
    const float* __restrict__ heads, const float* __restrict__ rw,
    const float* __restrict__ rr, float* __restrict__ qw, float* __restrict__ qr)
{
    int idx = blockIdx.x * 256 + threadIdx.x;
    int m = idx >> 9, c = idx & 511;
    float q = heads[(size_t)m * 1536 + c];
    qw[idx] = q + rw[c];
    qr[idx] = q + rr[c];
}

__global__ void __launch_bounds__(256) pos_kernel(float* __restrict__ pos)
{
    int p = blockIdx.x;
    int f = threadIdx.x;
    float ps = (float)(TTT - 1 - p);
    float invf = 1.0f / powf(10000.0f, (float)(2 * f) / (float)DM);
    float ang = ps * invf;
    pos[(size_t)p * DM + f]       = sinf(ang);
    pos[(size_t)p * DM + 256 + f] = cosf(ang);
}

__global__ void transpose_x(const float* __restrict__ x, float* __restrict__ xT)
{
    __shared__ float tile[32][33];
    int b = blockIdx.z;
    int t0 = blockIdx.x * 32, c0 = blockIdx.y * 32;
    int tx = threadIdx.x, ty = threadIdx.y;
#pragma unroll
    for (int i = 0; i < 4; i++) {
        int c = c0 + ty + i * 8;
        tile[ty + i * 8][tx] = x[((size_t)b * CIN + c) * TTT + t0 + tx];
    }
    __syncthreads();
#pragma unroll
    for (int i = 0; i < 4; i++) {
        int t = t0 + ty + i * 8;
        xT[((size_t)b * TTT + t) * CIN + c0 + tx] = tile[tx][ty + i * 8];
    }
}

__global__ void transpose_cls(const float* __restrict__ tmp, float* __restrict__ outp)
{
    __shared__ float tile[32][33];
    int b = blockIdx.z;
    int t0 = blockIdx.x * 32, k0 = blockIdx.y * 32;
    int tx = threadIdx.x, ty = threadIdx.y;
#pragma unroll
    for (int i = 0; i < 4; i++) {
        int t = t0 + ty + i * 8;
        tile[ty + i * 8][tx] = tmp[((size_t)b * TTT + t) * NCLS + k0 + tx];
    }
    __syncthreads();
#pragma unroll
    for (int i = 0; i < 4; i++) {
        int k = k0 + ty + i * 8;
        outp[((size_t)b * NCLS + k) * TTT + t0 + tx] = tile[tx][ty + i * 8];
    }
}

// ---------------- host orchestration ----------------
extern "C" void kernel_launch(void* const* d_in, const int* in_sizes, int n_in,
                              void* d_out, int out_size)
{
    const float* x        = (const float*)d_in[0];
    const float* emb_w    = (const float*)d_in[1];
    const float* emb_b    = (const float*)d_in[2];
    const float* r_w_bias = (const float*)d_in[3];
    const float* r_r_bias = (const float*)d_in[4];
    const float* qkv_w    = (const float*)d_in[5];
    const float* qkv_b    = (const float*)d_in[6];
    const float* r_proj_w = (const float*)d_in[7];
    const float* o_w      = (const float*)d_in[8];
    const float* ln1_s    = (const float*)d_in[9];
    const float* ln1_b    = (const float*)d_in[10];
    const float* ff1_w    = (const float*)d_in[11];
    const float* ff1_b    = (const float*)d_in[12];
    const float* ff2_w    = (const float*)d_in[13];
    const float* ff2_b    = (const float*)d_in[14];
    const float* ln2_s    = (const float*)d_in[15];
    const float* ln2_b    = (const float*)d_in[16];
    const float* cls_w    = (const float*)d_in[17];
    const float* cls_b    = (const float*)d_in[18];
    float* outp = (float*)d_out;

    float *xT, *h, *tmp, *heads, *qw, *qr, *rk, *pos, *ff, *Bx, *av, *cls;
    cudaGetSymbolAddress((void**)&xT, g_xT);
    cudaGetSymbolAddress((void**)&h, g_h);
    cudaGetSymbolAddress((void**)&tmp, g_tmp);
    cudaGetSymbolAddress((void**)&heads, g_heads);
    cudaGetSymbolAddress((void**)&qw, g_qw);
    cudaGetSymbolAddress((void**)&qr, g_qr);
    cudaGetSymbolAddress((void**)&rk, g_rk);
    cudaGetSymbolAddress((void**)&pos, g_pos);
    cudaGetSymbolAddress((void**)&ff, g_ff);
    cudaGetSymbolAddress((void**)&Bx, g_Bx);
    cudaGetSymbolAddress((void**)&av, g_av);
    cudaGetSymbolAddress((void**)&cls, g_cls);

    cudaFuncSetAttribute(gemm_tf32, cudaFuncAttributeMaxDynamicSharedMemorySize, GEMM_SMEM);
    cudaFuncSetAttribute(flash_attn, cudaFuncAttributeMaxDynamicSharedMemorySize, FA_SMEM);

    const float scale = 1.0f / 8.0f;

    transpose_x<<<dim3(TTT / 32, CIN / 32, BB), dim3(32, 8)>>>(x, xT);
    pos_kernel<<<TTT, 256>>>(pos);

    // embed: h = xT @ emb_w^T + emb_b
    gemm_tf32<<<dim3(4, 32, 1), 256, GEMM_SMEM>>>(
        xT, CIN, 0, 0, emb_w, CIN, 0, 0, emb_b, h, DM, 0, 0, MR, DM, CIN, 0);

    for (int l = 0; l < NLAY; l++) {
        const float* qkvW = qkv_w + (size_t)l * 3 * DM * DM;
        const float* qkvB = qkv_b + (size_t)l * 3 * DM;
        const float* rW   = r_proj_w + (size_t)l * DM * DM;
        const float* oW   = o_w + (size_t)l * DM * DM;
        const float* f1W  = ff1_w + (size_t)l * DI * DM;
        const float* f1B  = ff1_b + (size_t)l * DI;
        const float* f2W  = ff2_w + (size_t)l * DM * DI;
        const float* f2B  = ff2_b + (size_t)l * DM;

        // heads = h @ qkv_w^T + b
        gemm_tf32<<<dim3(12, 32, 1), 256, GEMM_SMEM>>>(
            h, DM, 0, 0, qkvW, DM, 0, 0, qkvB, heads, 3 * DM, 0, 0, MR, 3 * DM, DM, 0);

        make_qwr<<<(MR * DM) / 256, 256>>>(heads, r_w_bias, r_r_bias, qw, qr);

        // rk = pos @ r_proj_w^T
        gemm_tf32<<<dim3(4, 16, 1), 256, GEMM_SMEM>>>(
            pos, DM, 0, 0, rW, DM, 0, 0, nullptr, rk, DM, 0, 0, TTT, DM, DM, 0);

        // Bx[b,n] = qr @ rk_n^T  (unshifted position scores)
        gemm_tf32<<<dim3(16, 16, BB * NHD), 256, GEMM_SMEM>>>(
            qr, DM, (size_t)TTT * DM, 64,
            rk, DM, 0, 64,
            nullptr,
            Bx, TTT, (size_t)NHD * TTT * TTT, (size_t)TTT * TTT,
            TTT, TTT, 64, 0);

        // fused: av = softmax((qw K^T + shift(Bx)) * scale) @ V
        flash_attn<<<dim3(TTT / 128, BB * NHD), 256, FA_SMEM>>>(qw, heads, Bx, av, scale);

        // attn_out = av @ o_w^T
        gemm_tf32<<<dim3(4, 32, 1), 256, GEMM_SMEM>>>(
            av, DM, 0, 0, oW, DM, 0, 0, nullptr, tmp, DM, 0, 0, MR, DM, DM, 0);

        add_ln<<<MR, 128>>>(h, tmp, ln1_s + l * DM, ln1_b + l * DM);

        // ff = relu(h @ ff1_w^T + b)
        gemm_tf32<<<dim3(16, 32, 1), 256, GEMM_SMEM>>>(
            h, DM, 0, 0, f1W, DM, 0, 0, f1B, ff, DI, 0, 0, MR, DI, DM, 1);

        // tmp = ff @ ff2_w^T + b
        gemm_tf32<<<dim3(4, 32, 1), 256, GEMM_SMEM>>>(
            ff, DI, 0, 0, f2W, DI, 0, 0, f2B, tmp, DM, 0, 0, MR, DM, DI, 0);

        add_ln<<<MR, 128>>>(h, tmp, ln2_s + l * DM, ln2_b + l * DM);
    }

    // cls = h @ cls_w^T + b
    gemm_tf32<<<dim3(1, 32, 1), 256, GEMM_SMEM>>>(
        h, DM, 0, 0, cls_w, DM, 0, 0, cls_b, cls, NCLS, 0, 0, MR, NCLS, DM, 0);

    transpose_cls<<<dim3(TTT / 32, NCLS / 32, BB), dim3(32, 8)>>>(cls, outp);
}

// round 6
// speedup vs baseline: 3.7894x; 1.6262x over previous
#include <cuda_runtime.h>

// ---------------- problem constants ----------------
#define BB   2
#define TTT  2048
#define DM   512
#define NHD  8
#define DHD  64
#define NLAY 4
#define DI   2048
#define CIN  2048
#define NCLS 64
#define MR   (BB * TTT)   // 4096 token rows

// ---------------- scratch (device globals; no allocation allowed) ----------------
__device__ float g_xT[(size_t)BB * TTT * CIN];
__device__ float g_h[(size_t)MR * DM];
__device__ float g_tmp[(size_t)MR * DM];
__device__ float g_heads[(size_t)MR * 3 * DM];
__device__ float g_qw[(size_t)MR * DM];
__device__ float g_qr[(size_t)MR * DM];
__device__ float g_rk[(size_t)TTT * DM];
__device__ float g_pos[(size_t)TTT * DM];
__device__ float g_ff[(size_t)MR * DI];
__device__ float g_Bx[(size_t)BB * NHD * TTT * TTT];   // SHIFTED position scores (BDs layout)
__device__ float g_av[(size_t)MR * DM];
__device__ float g_cls[(size_t)MR * NCLS];

// ---------------- tf32 / cp.async helpers ----------------
__device__ __forceinline__ unsigned f2tf(float x) {
    unsigned u;
    asm("cvt.rna.tf32.f32 %0, %1;" : "=r"(u) : "f"(x));
    return u;
}

__device__ __forceinline__ void mma_tf32(float* c, const unsigned* a, const unsigned* b) {
    asm volatile(
        "mma.sync.aligned.m16n8k8.row.col.f32.tf32.tf32.f32 "
        "{%0,%1,%2,%3}, {%4,%5,%6,%7}, {%8,%9}, {%0,%1,%2,%3};"
        : "+f"(c[0]), "+f"(c[1]), "+f"(c[2]), "+f"(c[3])
        : "r"(a[0]), "r"(a[1]), "r"(a[2]), "r"(a[3]), "r"(b[0]), "r"(b[1]));
}

__device__ __forceinline__ void cp16(void* dst, const void* src, int srcbytes) {
    unsigned u = (unsigned)__cvta_generic_to_shared(dst);
    asm volatile("cp.async.cg.shared.global [%0], [%1], 16, %2;"
                 :: "r"(u), "l"(src), "r"(srcbytes));
}
__device__ __forceinline__ void cp_commit() {
    asm volatile("cp.async.commit_group;");
}

// ---------------- TF32 tensor-core GEMM, 2-stage cp.async pipeline ----------------
// C[M,N] = A[M,K] @ B^T (+bias)(+relu). A[m][k], B[n][k] row-major.
// M % 128 == 0, K % 32 == 0. N predicated.
#define GSM_STAGE (128 * 36)
#define GEMM_SMEM (4 * GSM_STAGE * 4)   // 73728 B

__global__ void __launch_bounds__(256) gemm_tf32(
    const float* __restrict__ A, int lda, size_t sAb, size_t sAn,
    const float* __restrict__ B, int ldb, size_t sBb, size_t sBn,
    const float* __restrict__ bias,
    float* __restrict__ C, int ldc, size_t sCb, size_t sCn,
    int M, int N, int K, int relu)
{
    const int z = blockIdx.z, zb = z >> 3, zn = z & 7;
    A += (size_t)zb * sAb + (size_t)zn * sAn;
    B += (size_t)zb * sBb + (size_t)zn * sBn;
    C += (size_t)zb * sCb + (size_t)zn * sCn;

    extern __shared__ float gsm[];
    float* AsBase = gsm;
    float* BsBase = gsm + 2 * GSM_STAGE;

    const int tid = threadIdx.x;
    const int warp = tid >> 5, lane = tid & 31;
    const int wm = warp >> 2, wn = warp & 3;
    const int g = lane >> 2, tg = lane & 3;
    const int m0 = blockIdx.y * 128, n0 = blockIdx.x * 128;

    float acc[4][4][4];
#pragma unroll
    for (int mt = 0; mt < 4; mt++)
#pragma unroll
        for (int nt = 0; nt < 4; nt++)
#pragma unroll
            for (int i = 0; i < 4; i++) acc[mt][nt][i] = 0.f;

    const int KT = K >> 5;

    auto load_stage = [&](int st, int k0) {
#pragma unroll
        for (int i = 0; i < 4; i++) {
            int idx = tid + i * 256;
            int row = idx >> 3;
            int kq = (idx & 7) * 4;
            cp16(&AsBase[st * GSM_STAGE + row * 36 + kq],
                 A + (size_t)(m0 + row) * lda + k0 + kq, 16);
        }
#pragma unroll
        for (int i = 0; i < 4; i++) {
            int idx = tid + i * 256;
            int row = idx >> 3;
            int kq = (idx & 7) * 4;
            int ok = (n0 + row) < N;
            cp16(&BsBase[st * GSM_STAGE + row * 36 + kq],
                 B + (size_t)(ok ? (n0 + row) : 0) * ldb + k0 + kq, ok ? 16 : 0);
        }
        cp_commit();
    };

    load_stage(0, 0);

    for (int kt = 0; kt < KT; kt++) {
        const int st = kt & 1;
        if (kt + 1 < KT) {
            load_stage(st ^ 1, (kt + 1) * 32);
            asm volatile("cp.async.wait_group 1;");
        } else {
            asm volatile("cp.async.wait_group 0;");
        }
        __syncthreads();

        const float* Asl = AsBase + st * GSM_STAGE;
        const float* Bsl = BsBase + st * GSM_STAGE;

#pragma unroll
        for (int ks = 0; ks < 4; ks++) {
            const int kk = ks * 8;
            unsigned a[4][4], bb[4][2];
#pragma unroll
            for (int mt = 0; mt < 4; mt++) {
                int r = wm * 64 + mt * 16;
                a[mt][0] = f2tf(Asl[(r + g) * 36 + kk + tg]);
                a[mt][1] = f2tf(Asl[(r + g + 8) * 36 + kk + tg]);
                a[mt][2] = f2tf(Asl[(r + g) * 36 + kk + tg + 4]);
                a[mt][3] = f2tf(Asl[(r + g + 8) * 36 + kk + tg + 4]);
            }
#pragma unroll
            for (int nt = 0; nt < 4; nt++) {
                int c = wn * 32 + nt * 8;
                bb[nt][0] = f2tf(Bsl[(c + g) * 36 + kk + tg]);
                bb[nt][1] = f2tf(Bsl[(c + g) * 36 + kk + tg + 4]);
            }
#pragma unroll
            for (int mt = 0; mt < 4; mt++)
#pragma unroll
                for (int nt = 0; nt < 4; nt++)
                    mma_tf32(acc[mt][nt], a[mt], bb[nt]);
        }
        __syncthreads();
    }

#pragma unroll
    for (int mt = 0; mt < 4; mt++) {
        int r0 = m0 + wm * 64 + mt * 16 + g;
#pragma unroll
        for (int nt = 0; nt < 4; nt++) {
            int c0 = n0 + wn * 32 + nt * 8 + tg * 2;
            if (c0 < N) {
                float b0v = bias ? bias[c0] : 0.f;
                float b1v = bias ? bias[c0 + 1] : 0.f;
                float v0 = acc[mt][nt][0] + b0v;
                float v1 = acc[mt][nt][1] + b1v;
                float v2 = acc[mt][nt][2] + b0v;
                float v3 = acc[mt][nt][3] + b1v;
                if (relu) {
                    v0 = fmaxf(v0, 0.f); v1 = fmaxf(v1, 0.f);
                    v2 = fmaxf(v2, 0.f); v3 = fmaxf(v3, 0.f);
                }
                *(float2*)(C + (size_t)r0 * ldc + c0) = make_float2(v0, v1);
                *(float2*)(C + (size_t)(r0 + 8) * ldc + c0) = make_float2(v2, v3);
            }
        }
    }
}

// ---------------- BD GEMM with shifted-scatter epilogue ----------------
// Computes Bx[i,c] = qr_i . rk_c and stores directly in rel-shifted layout:
//   c >= T-1-i : BDs[i][c-(T-1-i)]       (j = c-T+1+i <= i)
//   c <  T-1-i : BDs[i-1][c+i+1]         (wrap region, row i-1, j >= i+1... j = c+i+1)
// Slot BDs[i][i+1] is never written (semantically zero; consumer selects 0).
__device__ __forceinline__ void bd_store(float* __restrict__ BDs, int i, int c, float v) {
    int thr = TTT - 1 - i;
    if (c >= thr)      BDs[(size_t)i * TTT + (c - thr)] = v;
    else if (i > 0)    BDs[(size_t)(i - 1) * TTT + (c + i + 1)] = v;
}

__global__ void __launch_bounds__(256) gemm_bd(
    const float* __restrict__ A, int lda, size_t sAb, size_t sAn,   // qr
    const float* __restrict__ B, int ldb, size_t sBn,               // rk
    float* __restrict__ C, size_t sCbn)                             // BDs
{
    const int z = blockIdx.z, zb = z >> 3, zn = z & 7;
    A += (size_t)zb * sAb + (size_t)zn * sAn;
    B += (size_t)zn * sBn;
    C += (size_t)z * sCbn;

    extern __shared__ float gsm[];
    float* AsBase = gsm;
    float* BsBase = gsm + 2 * GSM_STAGE;

    const int tid = threadIdx.x;
    const int warp = tid >> 5, lane = tid & 31;
    const int wm = warp >> 2, wn = warp & 3;
    const int g = lane >> 2, tg = lane & 3;
    const int m0 = blockIdx.y * 128, n0 = blockIdx.x * 128;

    float acc[4][4][4];
#pragma unroll
    for (int mt = 0; mt < 4; mt++)
#pragma unroll
        for (int nt = 0; nt < 4; nt++)
#pragma unroll
            for (int i = 0; i < 4; i++) acc[mt][nt][i] = 0.f;

    auto load_stage = [&](int st, int k0) {
#pragma unroll
        for (int i = 0; i < 4; i++) {
            int idx = tid + i * 256;
            int row = idx >> 3;
            int kq = (idx & 7) * 4;
            cp16(&AsBase[st * GSM_STAGE + row * 36 + kq],
                 A + (size_t)(m0 + row) * lda + k0 + kq, 16);
        }
#pragma unroll
        for (int i = 0; i < 4; i++) {
            int idx = tid + i * 256;
            int row = idx >> 3;
            int kq = (idx & 7) * 4;
            cp16(&BsBase[st * GSM_STAGE + row * 36 + kq],
                 B + (size_t)(n0 + row) * ldb + k0 + kq, 16);
        }
        cp_commit();
    };

    load_stage(0, 0);

    // K = 64 -> 2 k-tiles
#pragma unroll
    for (int kt = 0; kt < 2; kt++) {
        const int st = kt & 1;
        if (kt == 0) {
            load_stage(1, 32);
            asm volatile("cp.async.wait_group 1;");
        } else {
            asm volatile("cp.async.wait_group 0;");
        }
        __syncthreads();

        const float* Asl = AsBase + st * GSM_STAGE;
        const float* Bsl = BsBase + st * GSM_STAGE;

#pragma unroll
        for (int ks = 0; ks < 4; ks++) {
            const int kk = ks * 8;
            unsigned a[4][4], bb[4][2];
#pragma unroll
            for (int mt = 0; mt < 4; mt++) {
                int r = wm * 64 + mt * 16;
                a[mt][0] = f2tf(Asl[(r + g) * 36 + kk + tg]);
                a[mt][1] = f2tf(Asl[(r + g + 8) * 36 + kk + tg]);
                a[mt][2] = f2tf(Asl[(r + g) * 36 + kk + tg + 4]);
                a[mt][3] = f2tf(Asl[(r + g + 8) * 36 + kk + tg + 4]);
            }
#pragma unroll
            for (int nt = 0; nt < 4; nt++) {
                int c = wn * 32 + nt * 8;
                bb[nt][0] = f2tf(Bsl[(c + g) * 36 + kk + tg]);
                bb[nt][1] = f2tf(Bsl[(c + g) * 36 + kk + tg + 4]);
            }
#pragma unroll
            for (int mt = 0; mt < 4; mt++)
#pragma unroll
                for (int nt = 0; nt < 4; nt++)
                    mma_tf32(acc[mt][nt], a[mt], bb[nt]);
        }
        __syncthreads();
    }

    // scatter epilogue into shifted layout
#pragma unroll
    for (int mt = 0; mt < 4; mt++) {
        int i0r = m0 + wm * 64 + mt * 16 + g;
        int i1r = i0r + 8;
#pragma unroll
        for (int nt = 0; nt < 4; nt++) {
            int c0 = n0 + wn * 32 + nt * 8 + tg * 2;
            bd_store(C, i0r, c0,     acc[mt][nt][0]);
            bd_store(C, i0r, c0 + 1, acc[mt][nt][1]);
            bd_store(C, i1r, c0,     acc[mt][nt][2]);
            bd_store(C, i1r, c0 + 1, acc[mt][nt][3]);
        }
    }
}

// ---------------- fused flash attention (BD pre-shifted, coalesced reads) ----------------
// smem: sP (tf32) [128][68] | sK (float) [2][64][68] | sV (float) [2][64][72]
#define SP_ELEMS (128 * 68)
#define SK_ELEMS (64 * 68)
#define SV_ELEMS (64 * 72)
#define FA_SMEM ((SP_ELEMS + 2 * SK_ELEMS + 2 * SV_ELEMS) * 4)

__global__ void __launch_bounds__(256, 1) flash_attn(
    const float* __restrict__ qw,     // [MR][512]
    const float* __restrict__ heads,  // [MR][1536]; K at +512, V at +1024
    const float* __restrict__ BDs,    // [16][T][T] pre-shifted
    float* __restrict__ av,           // [MR][512]
    float scale)
{
    extern __shared__ unsigned smem_u[];
    unsigned* sP = smem_u;                                   // [128][68]
    float* sK = (float*)(smem_u + SP_ELEMS);                 // [2][64][68]
    float* sV = (float*)(smem_u + SP_ELEMS) + 2 * SK_ELEMS;  // [2][64][72]

    const int tid = threadIdx.x;
    const int w = tid >> 5, lane = tid & 31;
    const int g = lane >> 2, tg = lane & 3;
    const int i0 = blockIdx.x * 128;
    const int bn = blockIdx.y;
    const int b = bn >> 3, n = bn & 7;

    const float* Qb = qw + ((size_t)b * TTT) * DM + n * 64;
    const float* Kb = heads + DM + ((size_t)b * TTT) * (3 * DM) + n * 64;
    const float* Vb = heads + 2 * DM + ((size_t)b * TTT) * (3 * DM) + n * 64;
    const float* Bb = BDs + (size_t)bn * TTT * TTT;

    auto kv_load = [&](int st, int j0) {
#pragma unroll
        for (int it = 0; it < 4; it++) {
            int idx = tid + it * 256;
            int row = idx >> 4, c4 = (idx & 15) * 4;
            cp16(&sK[st * SK_ELEMS + row * 68 + c4],
                 Kb + (size_t)(j0 + row) * (3 * DM) + c4, 16);
        }
#pragma unroll
        for (int it = 0; it < 4; it++) {
            int idx = tid + it * 256;
            int row = idx >> 4, c4 = (idx & 15) * 4;
            cp16(&sV[st * SV_ELEMS + row * 72 + c4],
                 Vb + (size_t)(j0 + row) * (3 * DM) + c4, 16);
        }
        cp_commit();
    };

    kv_load(0, 0);

#pragma unroll
    for (int it = 0; it < 8; it++) {
        int idx = tid + it * 256;
        int row = idx >> 4, c4 = (idx & 15) * 4;
        float4 v = *(const float4*)(Qb + (size_t)(i0 + row) * DM + c4);
        sP[row * 68 + c4 + 0] = f2tf(v.x);
        sP[row * 68 + c4 + 1] = f2tf(v.y);
        sP[row * 68 + c4 + 2] = f2tf(v.z);
        sP[row * 68 + c4 + 3] = f2tf(v.w);
    }
    __syncthreads();

    const int r0 = 16 * w + g;
    const int iR0 = i0 + r0, iR1 = iR0 + 8;
    const float* BDr0 = Bb + (size_t)iR0 * TTT;
    const float* BDr1 = Bb + (size_t)iR1 * TTT;

    unsigned qa[8][4];
#pragma unroll
    for (int kf = 0; kf < 8; kf++) {
        qa[kf][0] = sP[r0 * 68 + kf * 8 + tg];
        qa[kf][1] = sP[(r0 + 8) * 68 + kf * 8 + tg];
        qa[kf][2] = sP[r0 * 68 + kf * 8 + tg + 4];
        qa[kf][3] = sP[(r0 + 8) * 68 + kf * 8 + tg + 4];
    }

    float Oacc[8][4];
#pragma unroll
    for (int nf = 0; nf < 8; nf++)
#pragma unroll
        for (int i = 0; i < 4; i++) Oacc[nf][i] = 0.f;
    float mr0 = -1e30f, mr1 = -1e30f, lr0 = 0.f, lr1 = 0.f;

    for (int jt = 0; jt < TTT / 64; jt++) {
        const int st = jt & 1;
        const int j0 = jt * 64;
        if (jt + 1 < TTT / 64) {
            kv_load(st ^ 1, (jt + 1) * 64);
            asm volatile("cp.async.wait_group 1;");
        } else {
            asm volatile("cp.async.wait_group 0;");
        }
        __syncthreads();

        const float* Ks = sK + st * SK_ELEMS;
        const float* Vs = sV + st * SV_ELEMS;

        // ---- issue BD row loads early (coalesced, overlap with S MMAs)
        float2 y0v[8], y1v[8];
#pragma unroll
        for (int nf = 0; nf < 8; nf++) {
            int j = j0 + nf * 8 + 2 * tg;
            y0v[nf] = *(const float2*)(BDr0 + j);
            y1v[nf] = *(const float2*)(BDr1 + j);
        }

        // ---- S = Q @ K^T
        float s[8][4];
#pragma unroll
        for (int nf = 0; nf < 8; nf++)
#pragma unroll
            for (int i = 0; i < 4; i++) s[nf][i] = 0.f;
#pragma unroll
        for (int kf = 0; kf < 8; kf++) {
            const int kk = kf * 8;
#pragma unroll
            for (int nf = 0; nf < 8; nf++) {
                unsigned bb[2];
                bb[0] = f2tf(Ks[(nf * 8 + g) * 68 + kk + tg]);
                bb[1] = f2tf(Ks[(nf * 8 + g) * 68 + kk + tg + 4]);
                mma_tf32(s[nf], qa[kf], bb);
            }
        }

        // ---- add shifted BD (zero slot j == i+1 never written), scale
#pragma unroll
        for (int nf = 0; nf < 8; nf++) {
            int j = j0 + nf * 8 + 2 * tg;
            float b00 = (j     == iR0 + 1) ? 0.f : y0v[nf].x;
            float b01 = (j + 1 == iR0 + 1) ? 0.f : y0v[nf].y;
            float b10 = (j     == iR1 + 1) ? 0.f : y1v[nf].x;
            float b11 = (j + 1 == iR1 + 1) ? 0.f : y1v[nf].y;
            s[nf][0] = (s[nf][0] + b00) * scale;
            s[nf][1] = (s[nf][1] + b01) * scale;
            s[nf][2] = (s[nf][2] + b10) * scale;
            s[nf][3] = (s[nf][3] + b11) * scale;
        }

        // ---- online softmax
        float m0 = -1e30f, m1 = -1e30f;
#pragma unroll
        for (int nf = 0; nf < 8; nf++) {
            m0 = fmaxf(m0, fmaxf(s[nf][0], s[nf][1]));
            m1 = fmaxf(m1, fmaxf(s[nf][2], s[nf][3]));
        }
        m0 = fmaxf(m0, __shfl_xor_sync(0xffffffffu, m0, 1));
        m0 = fmaxf(m0, __shfl_xor_sync(0xffffffffu, m0, 2));
        m1 = fmaxf(m1, __shfl_xor_sync(0xffffffffu, m1, 1));
        m1 = fmaxf(m1, __shfl_xor_sync(0xffffffffu, m1, 2));
        float mn0 = fmaxf(mr0, m0), mn1 = fmaxf(mr1, m1);
        float a0 = __expf(mr0 - mn0), a1 = __expf(mr1 - mn1);

        float l0 = 0.f, l1 = 0.f;
#pragma unroll
        for (int nf = 0; nf < 8; nf++) {
            float p0 = __expf(s[nf][0] - mn0);
            float p1 = __expf(s[nf][1] - mn0);
            float p2 = __expf(s[nf][2] - mn1);
            float p3 = __expf(s[nf][3] - mn1);
            l0 += p0 + p1; l1 += p2 + p3;
            int c = nf * 8 + 2 * tg;
            sP[r0 * 68 + c]           = f2tf(p0);
            sP[r0 * 68 + c + 1]       = f2tf(p1);
            sP[(r0 + 8) * 68 + c]     = f2tf(p2);
            sP[(r0 + 8) * 68 + c + 1] = f2tf(p3);
        }
        l0 += __shfl_xor_sync(0xffffffffu, l0, 1);
        l0 += __shfl_xor_sync(0xffffffffu, l0, 2);
        l1 += __shfl_xor_sync(0xffffffffu, l1, 1);
        l1 += __shfl_xor_sync(0xffffffffu, l1, 2);
        lr0 = lr0 * a0 + l0;
        lr1 = lr1 * a1 + l1;
        mr0 = mn0; mr1 = mn1;
#pragma unroll
        for (int nf = 0; nf < 8; nf++) {
            Oacc[nf][0] *= a0; Oacc[nf][1] *= a0;
            Oacc[nf][2] *= a1; Oacc[nf][3] *= a1;
        }
        __syncwarp();

        // ---- O += P @ V
#pragma unroll
        for (int kf = 0; kf < 8; kf++) {
            const int kk = kf * 8;
            unsigned pa[4];
            pa[0] = sP[r0 * 68 + kk + tg];
            pa[1] = sP[(r0 + 8) * 68 + kk + tg];
            pa[2] = sP[r0 * 68 + kk + tg + 4];
            pa[3] = sP[(r0 + 8) * 68 + kk + tg + 4];
#pragma unroll
            for (int nf = 0; nf < 8; nf++) {
                unsigned bb[2];
                bb[0] = f2tf(Vs[(kk + tg) * 72 + nf * 8 + g]);
                bb[1] = f2tf(Vs[(kk + tg + 4) * 72 + nf * 8 + g]);
                mma_tf32(Oacc[nf], pa, bb);
            }
        }
        __syncthreads();
    }

    float inv0 = 1.f / lr0, inv1 = 1.f / lr1;
#pragma unroll
    for (int nf = 0; nf < 8; nf++) {
        int col = n * 64 + nf * 8 + 2 * tg;
        *(float2*)(av + (size_t)(b * TTT + iR0) * DM + col) =
            make_float2(Oacc[nf][0] * inv0, Oacc[nf][1] * inv0);
        *(float2*)(av + (size_t)(b * TTT + iR1) * DM + col) =
            make_float2(Oacc[nf][2] * inv1, Oacc[nf][3] * inv1);
    }
}

// ---------------- residual add + LayerNorm over d=512 ----------------
__global__ void __launch_bounds__(128) add_ln(
    float* __restrict__ h, const float* __restrict__ a,
    const float* __restrict__ gs, const float* __restrict__ gb)
{
    const int row = blockIdx.x, tid = threadIdx.x;
    float* hp = h + (size_t)row * DM;
    const float* ap = a + (size_t)row * DM;
    float v[4];
    float s = 0.f;
#pragma unroll
    for (int j = 0; j < 4; j++) { int c = tid + j * 128; v[j] = hp[c] + ap[c]; s += v[j]; }

    __shared__ float red[8];
#pragma unroll
    for (int o = 16; o > 0; o >>= 1) s += __shfl_xor_sync(0xffffffffu, s, o);
    if ((tid & 31) == 0) red[tid >> 5] = s;
    __syncthreads();
    float mean = (red[0] + red[1] + red[2] + red[3]) * (1.f / 512.f);

    float var = 0.f;
#pragma unroll
    for (int j = 0; j < 4; j++) { float d = v[j] - mean; var += d * d; }
#pragma unroll
    for (int o = 16; o > 0; o >>= 1) var += __shfl_xor_sync(0xffffffffu, var, o);
    if ((tid & 31) == 0) red[4 + (tid >> 5)] = var;
    __syncthreads();
    var = (red[4] + red[5] + red[6] + red[7]) * (1.f / 512.f);
    float rs = rsqrtf(var + 1e-5f);
#pragma unroll
    for (int j = 0; j < 4; j++) {
        int c = tid + j * 128;
        hp[c] = (v[j] - mean) * rs * gs[c] + gb[c];
    }
}

// ---------------- small helpers ----------------
__global__ void __launch_bounds__(256) make_qwr(
    const float* __restrict__ heads, const float* __restrict__ rw,
    const float* __restrict__ rr, float* __restrict__ qw, float* __restrict__ qr)
{
    int idx = blockIdx.x * 256 + threadIdx.x;
    int m = idx >> 9, c = idx & 511;
    float q = heads[(size_t)m * 1536 + c];
    qw[idx] = q + rw[c];
    qr[idx] = q + rr[c];
}

__global__ void __launch_bounds__(256) pos_kernel(float* __restrict__ pos)
{
    int p = blockIdx.x;
    int f = threadIdx.x;
    float ps = (float)(TTT - 1 - p);
    float invf = 1.0f / powf(10000.0f, (float)(2 * f) / (float)DM);
    float ang = ps * invf;
    pos[(size_t)p * DM + f]       = sinf(ang);
    pos[(size_t)p * DM + 256 + f] = cosf(ang);
}

__global__ void transpose_x(const float* __restrict__ x, float* __restrict__ xT)
{
    __shared__ float tile[32][33];
    int b = blockIdx.z;
    int t0 = blockIdx.x * 32, c0 = blockIdx.y * 32;
    int tx = threadIdx.x, ty = threadIdx.y;
#pragma unroll
    for (int i = 0; i < 4; i++) {
        int c = c0 + ty + i * 8;
        tile[ty + i * 8][tx] = x[((size_t)b * CIN + c) * TTT + t0 + tx];
    }
    __syncthreads();
#pragma unroll
    for (int i = 0; i < 4; i++) {
        int t = t0 + ty + i * 8;
        xT[((size_t)b * TTT + t) * CIN + c0 + tx] = tile[tx][ty + i * 8];
    }
}

__global__ void transpose_cls(const float* __restrict__ tmp, float* __restrict__ outp)
{
    __shared__ float tile[32][33];
    int b = blockIdx.z;
    int t0 = blockIdx.x * 32, k0 = blockIdx.y * 32;
    int tx = threadIdx.x, ty = threadIdx.y;
#pragma unroll
    for (int i = 0; i < 4; i++) {
        int t = t0 + ty + i * 8;
        tile[ty + i * 8][tx] = tmp[((size_t)b * TTT + t) * NCLS + k0 + tx];
    }
    __syncthreads();
#pragma unroll
    for (int i = 0; i < 4; i++) {
        int k = k0 + ty + i * 8;
        outp[((size_t)b * NCLS + k) * TTT + t0 + tx] = tile[tx][ty + i * 8];
    }
}

// ---------------- host orchestration ----------------
extern "C" void kernel_launch(void* const* d_in, const int* in_sizes, int n_in,
                              void* d_out, int out_size)
{
    const float* x        = (const float*)d_in[0];
    const float* emb_w    = (const float*)d_in[1];
    const float* emb_b    = (const float*)d_in[2];
    const float* r_w_bias = (const float*)d_in[3];
    const float* r_r_bias = (const float*)d_in[4];
    const float* qkv_w    = (const float*)d_in[5];
    const float* qkv_b    = (const float*)d_in[6];
    const float* r_proj_w = (const float*)d_in[7];
    const float* o_w      = (const float*)d_in[8];
    const float* ln1_s    = (const float*)d_in[9];
    const float* ln1_b    = (const float*)d_in[10];
    const float* ff1_w    = (const float*)d_in[11];
    const float* ff1_b    = (const float*)d_in[12];
    const float* ff2_w    = (const float*)d_in[13];
    const float* ff2_b    = (const float*)d_in[14];
    const float* ln2_s    = (const float*)d_in[15];
    const float* ln2_b    = (const float*)d_in[16];
    const float* cls_w    = (const float*)d_in[17];
    const float* cls_b    = (const float*)d_in[18];
    float* outp = (float*)d_out;

    float *xT, *h, *tmp, *heads, *qw, *qr, *rk, *pos, *ff, *Bx, *av, *cls;
    cudaGetSymbolAddress((void**)&xT, g_xT);
    cudaGetSymbolAddress((void**)&h, g_h);
    cudaGetSymbolAddress((void**)&tmp, g_tmp);
    cudaGetSymbolAddress((void**)&heads, g_heads);
    cudaGetSymbolAddress((void**)&qw, g_qw);
    cudaGetSymbolAddress((void**)&qr, g_qr);
    cudaGetSymbolAddress((void**)&rk, g_rk);
    cudaGetSymbolAddress((void**)&pos, g_pos);
    cudaGetSymbolAddress((void**)&ff, g_ff);
    cudaGetSymbolAddress((void**)&Bx, g_Bx);
    cudaGetSymbolAddress((void**)&av, g_av);
    cudaGetSymbolAddress((void**)&cls, g_cls);

    cudaFuncSetAttribute(gemm_tf32, cudaFuncAttributeMaxDynamicSharedMemorySize, GEMM_SMEM);
    cudaFuncSetAttribute(gemm_bd, cudaFuncAttributeMaxDynamicSharedMemorySize, GEMM_SMEM);
    cudaFuncSetAttribute(flash_attn, cudaFuncAttributeMaxDynamicSharedMemorySize, FA_SMEM);

    const float scale = 1.0f / 8.0f;

    transpose_x<<<dim3(TTT / 32, CIN / 32, BB), dim3(32, 8)>>>(x, xT);
    pos_kernel<<<TTT, 256>>>(pos);

    // embed: h = xT @ emb_w^T + emb_b
    gemm_tf32<<<dim3(4, 32, 1), 256, GEMM_SMEM>>>(
        xT, CIN, 0, 0, emb_w, CIN, 0, 0, emb_b, h, DM, 0, 0, MR, DM, CIN, 0);

    for (int l = 0; l < NLAY; l++) {
        const float* qkvW = qkv_w + (size_t)l * 3 * DM * DM;
        const float* qkvB = qkv_b + (size_t)l * 3 * DM;
        const float* rW   = r_proj_w + (size_t)l * DM * DM;
        const float* oW   = o_w + (size_t)l * DM * DM;
        const float* f1W  = ff1_w + (size_t)l * DI * DM;
        const float* f1B  = ff1_b + (size_t)l * DI;
        const float* f2W  = ff2_w + (size_t)l * DM * DI;
        const float* f2B  = ff2_b + (size_t)l * DM;

        // heads = h @ qkv_w^T + b
        gemm_tf32<<<dim3(12, 32, 1), 256, GEMM_SMEM>>>(
            h, DM, 0, 0, qkvW, DM, 0, 0, qkvB, heads, 3 * DM, 0, 0, MR, 3 * DM, DM, 0);

        make_qwr<<<(MR * DM) / 256, 256>>>(heads, r_w_bias, r_r_bias, qw, qr);

        // rk = pos @ r_proj_w^T
        gemm_tf32<<<dim3(4, 16, 1), 256, GEMM_SMEM>>>(
            pos, DM, 0, 0, rW, DM, 0, 0, nullptr, rk, DM, 0, 0, TTT, DM, DM, 0);

        // BDs[b,n] = rel_shift(qr @ rk_n^T)  -- scatter stored in shifted layout
        gemm_bd<<<dim3(16, 16, BB * NHD), 256, GEMM_SMEM>>>(
            qr, DM, (size_t)TTT * DM, 64,
            rk, DM, 64,
            Bx, (size_t)TTT * TTT);

        // fused: av = softmax((qw K^T + BDs) * scale) @ V
        flash_attn<<<dim3(TTT / 128, BB * NHD), 256, FA_SMEM>>>(qw, heads, Bx, av, scale);

        // attn_out = av @ o_w^T
        gemm_tf32<<<dim3(4, 32, 1), 256, GEMM_SMEM>>>(
            av, DM, 0, 0, oW, DM, 0, 0, nullptr, tmp, DM, 0, 0, MR, DM, DM, 0);

        add_ln<<<MR, 128>>>(h, tmp, ln1_s + l * DM, ln1_b + l * DM);

        // ff = relu(h @ ff1_w^T + b)
        gemm_tf32<<<dim3(16, 32, 1), 256, GEMM_SMEM>>>(
            h, DM, 0, 0, f1W, DM, 0, 0, f1B, ff, DI, 0, 0, MR, DI, DM, 1);

        // tmp = ff @ ff2_w^T + b
        gemm_tf32<<<dim3(4, 32, 1), 256, GEMM_SMEM>>>(
            ff, DI, 0, 0, f2W, DI, 0, 0, f2B, tmp, DM, 0, 0, MR, DM, DI, 0);

        add_ln<<<MR, 128>>>(h, tmp, ln2_s + l * DM, ln2_b + l * DM);
    }

    // cls = h @ cls_w^T + b
    gemm_tf32<<<dim3(1, 32, 1), 256, GEMM_SMEM>>>(
        h, DM, 0, 0, cls_w, DM, 0, 0, cls_b, cls, NCLS, 0, 0, MR, NCLS, DM, 0);

    transpose_cls<<<dim3(TTT / 32, NCLS / 32, BB), dim3(32, 8)>>>(cls, outp);
}

// round 7
// speedup vs baseline: 3.8086x; 1.0051x over previous
#include <cuda_runtime.h>

// ---------------- problem constants ----------------
#define BB   2
#define TTT  2048
#define DM   512
#define NHD  8
#define DHD  64
#define NLAY 4
#define DI   2048
#define CIN  2048
#define NCLS 64
#define MR   (BB * TTT)   // 4096 token rows

// ---------------- scratch (device globals; no allocation allowed) ----------------
__device__ float g_xT[(size_t)BB * TTT * CIN];
__device__ float g_h[(size_t)MR * DM];
__device__ float g_tmp[(size_t)MR * DM];
__device__ float g_heads[(size_t)MR * 3 * DM];
__device__ float g_qw[(size_t)MR * DM];
__device__ float g_qr[(size_t)MR * DM];
__device__ float g_rk[(size_t)TTT * DM];
__device__ float g_pos[(size_t)TTT * DM];
__device__ float g_ff[(size_t)MR * DI];
__device__ float g_Bx[(size_t)BB * NHD * TTT * TTT];   // SHIFTED position scores (BDs layout)
__device__ float g_av[(size_t)MR * DM];
__device__ float g_cls[(size_t)MR * NCLS];

// ---------------- tf32 / cp.async helpers ----------------
__device__ __forceinline__ unsigned f2tf(float x) {
    unsigned u;
    asm("cvt.rna.tf32.f32 %0, %1;" : "=r"(u) : "f"(x));
    return u;
}

__device__ __forceinline__ void mma_tf32(float* c, const unsigned* a, const unsigned* b) {
    asm volatile(
        "mma.sync.aligned.m16n8k8.row.col.f32.tf32.tf32.f32 "
        "{%0,%1,%2,%3}, {%4,%5,%6,%7}, {%8,%9}, {%0,%1,%2,%3};"
        : "+f"(c[0]), "+f"(c[1]), "+f"(c[2]), "+f"(c[3])
        : "r"(a[0]), "r"(a[1]), "r"(a[2]), "r"(a[3]), "r"(b[0]), "r"(b[1]));
}

__device__ __forceinline__ void cp16(void* dst, const void* src, int srcbytes) {
    unsigned u = (unsigned)__cvta_generic_to_shared(dst);
    asm volatile("cp.async.cg.shared.global [%0], [%1], 16, %2;"
                 :: "r"(u), "l"(src), "r"(srcbytes));
}
__device__ __forceinline__ void cp_commit() {
    asm volatile("cp.async.commit_group;");
}

// ---------------- TF32 tensor-core GEMM, 2-stage cp.async, 2 CTAs/SM ----------------
// C[M,N] = A[M,K] @ B^T (+bias)(+relu). A[m][k], B[n][k] row-major.
// Optional qkv-split epilogue: for global col < DM, also write qw = v + rwb, qr = v + rrb.
#define GSM_STAGE (128 * 36)
#define GEMM_SMEM (4 * GSM_STAGE * 4)   // 73728 B

__global__ void __launch_bounds__(256, 2) gemm_tf32(
    const float* __restrict__ A, int lda, size_t sAb, size_t sAn,
    const float* __restrict__ B, int ldb, size_t sBb, size_t sBn,
    const float* __restrict__ bias,
    float* __restrict__ C, int ldc, size_t sCb, size_t sCn,
    int M, int N, int K, int relu,
    const float* __restrict__ rwb, const float* __restrict__ rrb,
    float* __restrict__ qwO, float* __restrict__ qrO)
{
    const int z = blockIdx.z, zb = z >> 3, zn = z & 7;
    A += (size_t)zb * sAb + (size_t)zn * sAn;
    B += (size_t)zb * sBb + (size_t)zn * sBn;
    C += (size_t)zb * sCb + (size_t)zn * sCn;

    extern __shared__ float gsm[];
    float* AsBase = gsm;
    float* BsBase = gsm + 2 * GSM_STAGE;

    const int tid = threadIdx.x;
    const int warp = tid >> 5, lane = tid & 31;
    const int wm = warp >> 2, wn = warp & 3;
    const int g = lane >> 2, tg = lane & 3;
    const int m0 = blockIdx.y * 128, n0 = blockIdx.x * 128;

    float acc[4][4][4];
#pragma unroll
    for (int mt = 0; mt < 4; mt++)
#pragma unroll
        for (int nt = 0; nt < 4; nt++)
#pragma unroll
            for (int i = 0; i < 4; i++) acc[mt][nt][i] = 0.f;

    const int KT = K >> 5;

    auto load_stage = [&](int st, int k0) {
#pragma unroll
        for (int i = 0; i < 4; i++) {
            int idx = tid + i * 256;
            int row = idx >> 3;
            int kq = (idx & 7) * 4;
            cp16(&AsBase[st * GSM_STAGE + row * 36 + kq],
                 A + (size_t)(m0 + row) * lda + k0 + kq, 16);
        }
#pragma unroll
        for (int i = 0; i < 4; i++) {
            int idx = tid + i * 256;
            int row = idx >> 3;
            int kq = (idx & 7) * 4;
            int ok = (n0 + row) < N;
            cp16(&BsBase[st * GSM_STAGE + row * 36 + kq],
                 B + (size_t)(ok ? (n0 + row) : 0) * ldb + k0 + kq, ok ? 16 : 0);
        }
        cp_commit();
    };

    load_stage(0, 0);

    for (int kt = 0; kt < KT; kt++) {
        const int st = kt & 1;
        if (kt + 1 < KT) {
            load_stage(st ^ 1, (kt + 1) * 32);
            asm volatile("cp.async.wait_group 1;");
        } else {
            asm volatile("cp.async.wait_group 0;");
        }
        __syncthreads();

        const float* Asl = AsBase + st * GSM_STAGE;
        const float* Bsl = BsBase + st * GSM_STAGE;

#pragma unroll
        for (int ks = 0; ks < 4; ks++) {
            const int kk = ks * 8;
            unsigned a[4][4], bb[4][2];
#pragma unroll
            for (int mt = 0; mt < 4; mt++) {
                int r = wm * 64 + mt * 16;
                a[mt][0] = f2tf(Asl[(r + g) * 36 + kk + tg]);
                a[mt][1] = f2tf(Asl[(r + g + 8) * 36 + kk + tg]);
                a[mt][2] = f2tf(Asl[(r + g) * 36 + kk + tg + 4]);
                a[mt][3] = f2tf(Asl[(r + g + 8) * 36 + kk + tg + 4]);
            }
#pragma unroll
            for (int nt = 0; nt < 4; nt++) {
                int c = wn * 32 + nt * 8;
                bb[nt][0] = f2tf(Bsl[(c + g) * 36 + kk + tg]);
                bb[nt][1] = f2tf(Bsl[(c + g) * 36 + kk + tg + 4]);
            }
#pragma unroll
            for (int mt = 0; mt < 4; mt++)
#pragma unroll
                for (int nt = 0; nt < 4; nt++)
                    mma_tf32(acc[mt][nt], a[mt], bb[nt]);
        }
        __syncthreads();
    }

#pragma unroll
    for (int mt = 0; mt < 4; mt++) {
        int r0 = m0 + wm * 64 + mt * 16 + g;
#pragma unroll
        for (int nt = 0; nt < 4; nt++) {
            int c0 = n0 + wn * 32 + nt * 8 + tg * 2;
            if (c0 < N) {
                float b0v = bias ? bias[c0] : 0.f;
                float b1v = bias ? bias[c0 + 1] : 0.f;
                float v0 = acc[mt][nt][0] + b0v;
                float v1 = acc[mt][nt][1] + b1v;
                float v2 = acc[mt][nt][2] + b0v;
                float v3 = acc[mt][nt][3] + b1v;
                if (relu) {
                    v0 = fmaxf(v0, 0.f); v1 = fmaxf(v1, 0.f);
                    v2 = fmaxf(v2, 0.f); v3 = fmaxf(v3, 0.f);
                }
                *(float2*)(C + (size_t)r0 * ldc + c0) = make_float2(v0, v1);
                *(float2*)(C + (size_t)(r0 + 8) * ldc + c0) = make_float2(v2, v3);
                if (qwO && c0 < DM) {
                    float w0 = rwb[c0], w1 = rwb[c0 + 1];
                    float r0b = rrb[c0], r1b = rrb[c0 + 1];
                    *(float2*)(qwO + (size_t)r0 * DM + c0) = make_float2(v0 + w0, v1 + w1);
                    *(float2*)(qwO + (size_t)(r0 + 8) * DM + c0) = make_float2(v2 + w0, v3 + w1);
                    *(float2*)(qrO + (size_t)r0 * DM + c0) = make_float2(v0 + r0b, v1 + r1b);
                    *(float2*)(qrO + (size_t)(r0 + 8) * DM + c0) = make_float2(v2 + r0b, v3 + r1b);
                }
            }
        }
    }
}

// ---------------- BD GEMM with shifted-scatter epilogue ----------------
// Bx[i,c] = qr_i . rk_c stored directly in rel-shifted layout:
//   c >= T-1-i : BDs[i][c-(T-1-i)]
//   c <  T-1-i : BDs[i-1][c+i+1]
// Slot BDs[i][i+1] is never written (semantically zero; consumer selects 0).
__device__ __forceinline__ void bd_store(float* __restrict__ BDs, int i, int c, float v) {
    int thr = TTT - 1 - i;
    if (c >= thr)      BDs[(size_t)i * TTT + (c - thr)] = v;
    else if (i > 0)    BDs[(size_t)(i - 1) * TTT + (c + i + 1)] = v;
}

__global__ void __launch_bounds__(256, 2) gemm_bd(
    const float* __restrict__ A, int lda, size_t sAb, size_t sAn,   // qr
    const float* __restrict__ B, int ldb, size_t sBn,               // rk
    float* __restrict__ C, size_t sCbn)                             // BDs
{
    const int z = blockIdx.z, zb = z >> 3, zn = z & 7;
    A += (size_t)zb * sAb + (size_t)zn * sAn;
    B += (size_t)zn * sBn;
    C += (size_t)z * sCbn;

    extern __shared__ float gsm[];
    float* AsBase = gsm;
    float* BsBase = gsm + 2 * GSM_STAGE;

    const int tid = threadIdx.x;
    const int warp = tid >> 5, lane = tid & 31;
    const int wm = warp >> 2, wn = warp & 3;
    const int g = lane >> 2, tg = lane & 3;
    const int m0 = blockIdx.y * 128, n0 = blockIdx.x * 128;

    float acc[4][4][4];
#pragma unroll
    for (int mt = 0; mt < 4; mt++)
#pragma unroll
        for (int nt = 0; nt < 4; nt++)
#pragma unroll
            for (int i = 0; i < 4; i++) acc[mt][nt][i] = 0.f;

    auto load_stage = [&](int st, int k0) {
#pragma unroll
        for (int i = 0; i < 4; i++) {
            int idx = tid + i * 256;
            int row = idx >> 3;
            int kq = (idx & 7) * 4;
            cp16(&AsBase[st * GSM_STAGE + row * 36 + kq],
                 A + (size_t)(m0 + row) * lda + k0 + kq, 16);
        }
#pragma unroll
        for (int i = 0; i < 4; i++) {
            int idx = tid + i * 256;
            int row = idx >> 3;
            int kq = (idx & 7) * 4;
            cp16(&BsBase[st * GSM_STAGE + row * 36 + kq],
                 B + (size_t)(n0 + row) * ldb + k0 + kq, 16);
        }
        cp_commit();
    };

    load_stage(0, 0);

#pragma unroll
    for (int kt = 0; kt < 2; kt++) {
        const int st = kt & 1;
        if (kt == 0) {
            load_stage(1, 32);
            asm volatile("cp.async.wait_group 1;");
        } else {
            asm volatile("cp.async.wait_group 0;");
        }
        __syncthreads();

        const float* Asl = AsBase + st * GSM_STAGE;
        const float* Bsl = BsBase + st * GSM_STAGE;

#pragma unroll
        for (int ks = 0; ks < 4; ks++) {
            const int kk = ks * 8;
            unsigned a[4][4], bb[4][2];
#pragma unroll
            for (int mt = 0; mt < 4; mt++) {
                int r = wm * 64 + mt * 16;
                a[mt][0] = f2tf(Asl[(r + g) * 36 + kk + tg]);
                a[mt][1] = f2tf(Asl[(r + g + 8) * 36 + kk + tg]);
                a[mt][2] = f2tf(Asl[(r + g) * 36 + kk + tg + 4]);
                a[mt][3] = f2tf(Asl[(r + g + 8) * 36 + kk + tg + 4]);
            }
#pragma unroll
            for (int nt = 0; nt < 4; nt++) {
                int c = wn * 32 + nt * 8;
                bb[nt][0] = f2tf(Bsl[(c + g) * 36 + kk + tg]);
                bb[nt][1] = f2tf(Bsl[(c + g) * 36 + kk + tg + 4]);
            }
#pragma unroll
            for (int mt = 0; mt < 4; mt++)
#pragma unroll
                for (int nt = 0; nt < 4; nt++)
                    mma_tf32(acc[mt][nt], a[mt], bb[nt]);
        }
        __syncthreads();
    }

#pragma unroll
    for (int mt = 0; mt < 4; mt++) {
        int i0r = m0 + wm * 64 + mt * 16 + g;
        int i1r = i0r + 8;
#pragma unroll
        for (int nt = 0; nt < 4; nt++) {
            int c0 = n0 + wn * 32 + nt * 8 + tg * 2;
            bd_store(C, i0r, c0,     acc[mt][nt][0]);
            bd_store(C, i0r, c0 + 1, acc[mt][nt][1]);
            bd_store(C, i1r, c0,     acc[mt][nt][2]);
            bd_store(C, i1r, c0 + 1, acc[mt][nt][3]);
        }
    }
}

// ---------------- fused flash attention (BD pre-shifted, coalesced reads) ----------------
#define SP_ELEMS (128 * 68)
#define SK_ELEMS (64 * 68)
#define SV_ELEMS (64 * 72)
#define FA_SMEM ((SP_ELEMS + 2 * SK_ELEMS + 2 * SV_ELEMS) * 4)

__global__ void __launch_bounds__(256, 1) flash_attn(
    const float* __restrict__ qw,     // [MR][512]
    const float* __restrict__ heads,  // [MR][1536]; K at +512, V at +1024
    const float* __restrict__ BDs,    // [16][T][T] pre-shifted
    float* __restrict__ av,           // [MR][512]
    float scale)
{
    extern __shared__ unsigned smem_u[];
    unsigned* sP = smem_u;                                   // [128][68]
    float* sK = (float*)(smem_u + SP_ELEMS);                 // [2][64][68]
    float* sV = (float*)(smem_u + SP_ELEMS) + 2 * SK_ELEMS;  // [2][64][72]

    const int tid = threadIdx.x;
    const int w = tid >> 5, lane = tid & 31;
    const int g = lane >> 2, tg = lane & 3;
    const int i0 = blockIdx.x * 128;
    const int bn = blockIdx.y;
    const int b = bn >> 3, n = bn & 7;

    const float* Qb = qw + ((size_t)b * TTT) * DM + n * 64;
    const float* Kb = heads + DM + ((size_t)b * TTT) * (3 * DM) + n * 64;
    const float* Vb = heads + 2 * DM + ((size_t)b * TTT) * (3 * DM) + n * 64;
    const float* Bb = BDs + (size_t)bn * TTT * TTT;

    auto kv_load = [&](int st, int j0) {
#pragma unroll
        for (int it = 0; it < 4; it++) {
            int idx = tid + it * 256;
            int row = idx >> 4, c4 = (idx & 15) * 4;
            cp16(&sK[st * SK_ELEMS + row * 68 + c4],
                 Kb + (size_t)(j0 + row) * (3 * DM) + c4, 16);
        }
#pragma unroll
        for (int it = 0; it < 4; it++) {
            int idx = tid + it * 256;
            int row = idx >> 4, c4 = (idx & 15) * 4;
            cp16(&sV[st * SV_ELEMS + row * 72 + c4],
                 Vb + (size_t)(j0 + row) * (3 * DM) + c4, 16);
        }
        cp_commit();
    };

    kv_load(0, 0);

#pragma unroll
    for (int it = 0; it < 8; it++) {
        int idx = tid + it * 256;
        int row = idx >> 4, c4 = (idx & 15) * 4;
        float4 v = *(const float4*)(Qb + (size_t)(i0 + row) * DM + c4);
        sP[row * 68 + c4 + 0] = f2tf(v.x);
        sP[row * 68 + c4 + 1] = f2tf(v.y);
        sP[row * 68 + c4 + 2] = f2tf(v.z);
        sP[row * 68 + c4 + 3] = f2tf(v.w);
    }
    __syncthreads();

    const int r0 = 16 * w + g;
    const int iR0 = i0 + r0, iR1 = iR0 + 8;
    const float* BDr0 = Bb + (size_t)iR0 * TTT;
    const float* BDr1 = Bb + (size_t)iR1 * TTT;

    unsigned qa[8][4];
#pragma unroll
    for (int kf = 0; kf < 8; kf++) {
        qa[kf][0] = sP[r0 * 68 + kf * 8 + tg];
        qa[kf][1] = sP[(r0 + 8) * 68 + kf * 8 + tg];
        qa[kf][2] = sP[r0 * 68 + kf * 8 + tg + 4];
        qa[kf][3] = sP[(r0 + 8) * 68 + kf * 8 + tg + 4];
    }

    float Oacc[8][4];
#pragma unroll
    for (int nf = 0; nf < 8; nf++)
#pragma unroll
        for (int i = 0; i < 4; i++) Oacc[nf][i] = 0.f;
    float mr0 = -1e30f, mr1 = -1e30f, lr0 = 0.f, lr1 = 0.f;

    for (int jt = 0; jt < TTT / 64; jt++) {
        const int st = jt & 1;
        const int j0 = jt * 64;
        if (jt + 1 < TTT / 64) {
            kv_load(st ^ 1, (jt + 1) * 64);
            asm volatile("cp.async.wait_group 1;");
        } else {
            asm volatile("cp.async.wait_group 0;");
        }
        __syncthreads();

        const float* Ks = sK + st * SK_ELEMS;
        const float* Vs = sV + st * SV_ELEMS;

        // ---- issue BD row loads early (coalesced, overlap with S MMAs)
        float2 y0v[8], y1v[8];
#pragma unroll
        for (int nf = 0; nf < 8; nf++) {
            int j = j0 + nf * 8 + 2 * tg;
            y0v[nf] = *(const float2*)(BDr0 + j);
            y1v[nf] = *(const float2*)(BDr1 + j);
        }

        // ---- S = Q @ K^T
        float s[8][4];
#pragma unroll
        for (int nf = 0; nf < 8; nf++)
#pragma unroll
            for (int i = 0; i < 4; i++) s[nf][i] = 0.f;
#pragma unroll
        for (int kf = 0; kf < 8; kf++) {
            const int kk = kf * 8;
#pragma unroll
            for (int nf = 0; nf < 8; nf++) {
                unsigned bb[2];
                bb[0] = f2tf(Ks[(nf * 8 + g) * 68 + kk + tg]);
                bb[1] = f2tf(Ks[(nf * 8 + g) * 68 + kk + tg + 4]);
                mma_tf32(s[nf], qa[kf], bb);
            }
        }

        // ---- add shifted BD (zero slot j == i+1 never written), scale
#pragma unroll
        for (int nf = 0; nf < 8; nf++) {
            int j = j0 + nf * 8 + 2 * tg;
            float b00 = (j     == iR0 + 1) ? 0.f : y0v[nf].x;
            float b01 = (j + 1 == iR0 + 1) ? 0.f : y0v[nf].y;
            float b10 = (j     == iR1 + 1) ? 0.f : y1v[nf].x;
            float b11 = (j + 1 == iR1 + 1) ? 0.f : y1v[nf].y;
            s[nf][0] = (s[nf][0] + b00) * scale;
            s[nf][1] = (s[nf][1] + b01) * scale;
            s[nf][2] = (s[nf][2] + b10) * scale;
            s[nf][3] = (s[nf][3] + b11) * scale;
        }

        // ---- online softmax
        float m0 = -1e30f, m1 = -1e30f;
#pragma unroll
        for (int nf = 0; nf < 8; nf++) {
            m0 = fmaxf(m0, fmaxf(s[nf][0], s[nf][1]));
            m1 = fmaxf(m1, fmaxf(s[nf][2], s[nf][3]));
        }
        m0 = fmaxf(m0, __shfl_xor_sync(0xffffffffu, m0, 1));
        m0 = fmaxf(m0, __shfl_xor_sync(0xffffffffu, m0, 2));
        m1 = fmaxf(m1, __shfl_xor_sync(0xffffffffu, m1, 1));
        m1 = fmaxf(m1, __shfl_xor_sync(0xffffffffu, m1, 2));
        float mn0 = fmaxf(mr0, m0), mn1 = fmaxf(mr1, m1);
        float a0 = __expf(mr0 - mn0), a1 = __expf(mr1 - mn1);

        float l0 = 0.f, l1 = 0.f;
#pragma unroll
        for (int nf = 0; nf < 8; nf++) {
            float p0 = __expf(s[nf][0] - mn0);
            float p1 = __expf(s[nf][1] - mn0);
            float p2 = __expf(s[nf][2] - mn1);
            float p3 = __expf(s[nf][3] - mn1);
            l0 += p0 + p1; l1 += p2 + p3;
            int c = nf * 8 + 2 * tg;
            sP[r0 * 68 + c]           = f2tf(p0);
            sP[r0 * 68 + c + 1]       = f2tf(p1);
            sP[(r0 + 8) * 68 + c]     = f2tf(p2);
            sP[(r0 + 8) * 68 + c + 1] = f2tf(p3);
        }
        l0 += __shfl_xor_sync(0xffffffffu, l0, 1);
        l0 += __shfl_xor_sync(0xffffffffu, l0, 2);
        l1 += __shfl_xor_sync(0xffffffffu, l1, 1);
        l1 += __shfl_xor_sync(0xffffffffu, l1, 2);
        lr0 = lr0 * a0 + l0;
        lr1 = lr1 * a1 + l1;
        mr0 = mn0; mr1 = mn1;
#pragma unroll
        for (int nf = 0; nf < 8; nf++) {
            Oacc[nf][0] *= a0; Oacc[nf][1] *= a0;
            Oacc[nf][2] *= a1; Oacc[nf][3] *= a1;
        }
        __syncwarp();

        // ---- O += P @ V
#pragma unroll
        for (int kf = 0; kf < 8; kf++) {
            const int kk = kf * 8;
            unsigned pa[4];
            pa[0] = sP[r0 * 68 + kk + tg];
            pa[1] = sP[(r0 + 8) * 68 + kk + tg];
            pa[2] = sP[r0 * 68 + kk + tg + 4];
            pa[3] = sP[(r0 + 8) * 68 + kk + tg + 4];
#pragma unroll
            for (int nf = 0; nf < 8; nf++) {
                unsigned bb[2];
                bb[0] = f2tf(Vs[(kk + tg) * 72 + nf * 8 + g]);
                bb[1] = f2tf(Vs[(kk + tg + 4) * 72 + nf * 8 + g]);
                mma_tf32(Oacc[nf], pa, bb);
            }
        }
        __syncthreads();
    }

    float inv0 = 1.f / lr0, inv1 = 1.f / lr1;
#pragma unroll
    for (int nf = 0; nf < 8; nf++) {
        int col = n * 64 + nf * 8 + 2 * tg;
        *(float2*)(av + (size_t)(b * TTT + iR0) * DM + col) =
            make_float2(Oacc[nf][0] * inv0, Oacc[nf][1] * inv0);
        *(float2*)(av + (size_t)(b * TTT + iR1) * DM + col) =
            make_float2(Oacc[nf][2] * inv1, Oacc[nf][3] * inv1);
    }
}

// ---------------- residual add + LayerNorm over d=512 ----------------
__global__ void __launch_bounds__(128) add_ln(
    float* __restrict__ h, const float* __restrict__ a,
    const float* __restrict__ gs, const float* __restrict__ gb)
{
    const int row = blockIdx.x, tid = threadIdx.x;
    float* hp = h + (size_t)row * DM;
    const float* ap = a + (size_t)row * DM;
    float v[4];
    float s = 0.f;
#pragma unroll
    for (int j = 0; j < 4; j++) { int c = tid + j * 128; v[j] = hp[c] + ap[c]; s += v[j]; }

    __shared__ float red[8];
#pragma unroll
    for (int o = 16; o > 0; o >>= 1) s += __shfl_xor_sync(0xffffffffu, s, o);
    if ((tid & 31) == 0) red[tid >> 5] = s;
    __syncthreads();
    float mean = (red[0] + red[1] + red[2] + red[3]) * (1.f / 512.f);

    float var = 0.f;
#pragma unroll
    for (int j = 0; j < 4; j++) { float d = v[j] - mean; var += d * d; }
#pragma unroll
    for (int o = 16; o > 0; o >>= 1) var += __shfl_xor_sync(0xffffffffu, var, o);
    if ((tid & 31) == 0) red[4 + (tid >> 5)] = var;
    __syncthreads();
    var = (red[4] + red[5] + red[6] + red[7]) * (1.f / 512.f);
    float rs = rsqrtf(var + 1e-5f);
#pragma unroll
    for (int j = 0; j < 4; j++) {
        int c = tid + j * 128;
        hp[c] = (v[j] - mean) * rs * gs[c] + gb[c];
    }
}

// ---------------- small helpers ----------------
__global__ void __launch_bounds__(256) pos_kernel(float* __restrict__ pos)
{
    int p = blockIdx.x;
    int f = threadIdx.x;
    float ps = (float)(TTT - 1 - p);
    float invf = 1.0f / powf(10000.0f, (float)(2 * f) / (float)DM);
    float ang = ps * invf;
    pos[(size_t)p * DM + f]       = sinf(ang);
    pos[(size_t)p * DM + 256 + f] = cosf(ang);
}

__global__ void transpose_x(const float* __restrict__ x, float* __restrict__ xT)
{
    __shared__ float tile[32][33];
    int b = blockIdx.z;
    int t0 = blockIdx.x * 32, c0 = blockIdx.y * 32;
    int tx = threadIdx.x, ty = threadIdx.y;
#pragma unroll
    for (int i = 0; i < 4; i++) {
        int c = c0 + ty + i * 8;
        tile[ty + i * 8][tx] = x[((size_t)b * CIN + c) * TTT + t0 + tx];
    }
    __syncthreads();
#pragma unroll
    for (int i = 0; i < 4; i++) {
        int t = t0 + ty + i * 8;
        xT[((size_t)b * TTT + t) * CIN + c0 + tx] = tile[tx][ty + i * 8];
    }
}

__global__ void transpose_cls(const float* __restrict__ tmp, float* __restrict__ outp)
{
    __shared__ float tile[32][33];
    int b = blockIdx.z;
    int t0 = blockIdx.x * 32, k0 = blockIdx.y * 32;
    int tx = threadIdx.x, ty = threadIdx.y;
#pragma unroll
    for (int i = 0; i < 4; i++) {
        int t = t0 + ty + i * 8;
        tile[ty + i * 8][tx] = tmp[((size_t)b * TTT + t) * NCLS + k0 + tx];
    }
    __syncthreads();
#pragma unroll
    for (int i = 0; i < 4; i++) {
        int k = k0 + ty + i * 8;
        outp[((size_t)b * NCLS + k) * TTT + t0 + tx] = tile[tx][ty + i * 8];
    }
}

// ---------------- host orchestration ----------------
extern "C" void kernel_launch(void* const* d_in, const int* in_sizes, int n_in,
                              void* d_out, int out_size)
{
    const float* x        = (const float*)d_in[0];
    const float* emb_w    = (const float*)d_in[1];
    const float* emb_b    = (const float*)d_in[2];
    const float* r_w_bias = (const float*)d_in[3];
    const float* r_r_bias = (const float*)d_in[4];
    const float* qkv_w    = (const float*)d_in[5];
    const float* qkv_b    = (const float*)d_in[6];
    const float* r_proj_w = (const float*)d_in[7];
    const float* o_w      = (const float*)d_in[8];
    const float* ln1_s    = (const float*)d_in[9];
    const float* ln1_b    = (const float*)d_in[10];
    const float* ff1_w    = (const float*)d_in[11];
    const float* ff1_b    = (const float*)d_in[12];
    const float* ff2_w    = (const float*)d_in[13];
    const float* ff2_b    = (const float*)d_in[14];
    const float* ln2_s    = (const float*)d_in[15];
    const float* ln2_b    = (const float*)d_in[16];
    const float* cls_w    = (const float*)d_in[17];
    const float* cls_b    = (const float*)d_in[18];
    float* outp = (float*)d_out;

    float *xT, *h, *tmp, *heads, *qw, *qr, *rk, *pos, *ff, *Bx, *av, *cls;
    cudaGetSymbolAddress((void**)&xT, g_xT);
    cudaGetSymbolAddress((void**)&h, g_h);
    cudaGetSymbolAddress((void**)&tmp, g_tmp);
    cudaGetSymbolAddress((void**)&heads, g_heads);
    cudaGetSymbolAddress((void**)&qw, g_qw);
    cudaGetSymbolAddress((void**)&qr, g_qr);
    cudaGetSymbolAddress((void**)&rk, g_rk);
    cudaGetSymbolAddress((void**)&pos, g_pos);
    cudaGetSymbolAddress((void**)&ff, g_ff);
    cudaGetSymbolAddress((void**)&Bx, g_Bx);
    cudaGetSymbolAddress((void**)&av, g_av);
    cudaGetSymbolAddress((void**)&cls, g_cls);

    cudaFuncSetAttribute(gemm_tf32, cudaFuncAttributeMaxDynamicSharedMemorySize, GEMM_SMEM);
    cudaFuncSetAttribute(gemm_bd, cudaFuncAttributeMaxDynamicSharedMemorySize, GEMM_SMEM);
    cudaFuncSetAttribute(flash_attn, cudaFuncAttributeMaxDynamicSharedMemorySize, FA_SMEM);

    const float scale = 1.0f / 8.0f;

    transpose_x<<<dim3(TTT / 32, CIN / 32, BB), dim3(32, 8)>>>(x, xT);
    pos_kernel<<<TTT, 256>>>(pos);

    // embed: h = xT @ emb_w^T + emb_b
    gemm_tf32<<<dim3(4, 32, 1), 256, GEMM_SMEM>>>(
        xT, CIN, 0, 0, emb_w, CIN, 0, 0, emb_b, h, DM, 0, 0, MR, DM, CIN, 0,
        nullptr, nullptr, nullptr, nullptr);

    for (int l = 0; l < NLAY; l++) {
        const float* qkvW = qkv_w + (size_t)l * 3 * DM * DM;
        const float* qkvB = qkv_b + (size_t)l * 3 * DM;
        const float* rW   = r_proj_w + (size_t)l * DM * DM;
        const float* oW   = o_w + (size_t)l * DM * DM;
        const float* f1W  = ff1_w + (size_t)l * DI * DM;
        const float* f1B  = ff1_b + (size_t)l * DI;
        const float* f2W  = ff2_w + (size_t)l * DM * DI;
        const float* f2B  = ff2_b + (size_t)l * DM;

        // heads = h @ qkv_w^T + b ; fused qw/qr epilogue for q columns
        gemm_tf32<<<dim3(12, 32, 1), 256, GEMM_SMEM>>>(
            h, DM, 0, 0, qkvW, DM, 0, 0, qkvB, heads, 3 * DM, 0, 0, MR, 3 * DM, DM, 0,
            r_w_bias, r_r_bias, qw, qr);

        // rk = pos @ r_proj_w^T
        gemm_tf32<<<dim3(4, 16, 1), 256, GEMM_SMEM>>>(
            pos, DM, 0, 0, rW, DM, 0, 0, nullptr, rk, DM, 0, 0, TTT, DM, DM, 0,
            nullptr, nullptr, nullptr, nullptr);

        // BDs[b,n] = rel_shift(qr @ rk_n^T)  -- scatter stored in shifted layout
        gemm_bd<<<dim3(16, 16, BB * NHD), 256, GEMM_SMEM>>>(
            qr, DM, (size_t)TTT * DM, 64,
            rk, DM, 64,
            Bx, (size_t)TTT * TTT);

        // fused: av = softmax((qw K^T + BDs) * scale) @ V
        flash_attn<<<dim3(TTT / 128, BB * NHD), 256, FA_SMEM>>>(qw, heads, Bx, av, scale);

        // attn_out = av @ o_w^T
        gemm_tf32<<<dim3(4, 32, 1), 256, GEMM_SMEM>>>(
            av, DM, 0, 0, oW, DM, 0, 0, nullptr, tmp, DM, 0, 0, MR, DM, DM, 0,
            nullptr, nullptr, nullptr, nullptr);

        add_ln<<<MR, 128>>>(h, tmp, ln1_s + l * DM, ln1_b + l * DM);

        // ff = relu(h @ ff1_w^T + b)
        gemm_tf32<<<dim3(16, 32, 1), 256, GEMM_SMEM>>>(
            h, DM, 0, 0, f1W, DM, 0, 0, f1B, ff, DI, 0, 0, MR, DI, DM, 1,
            nullptr, nullptr, nullptr, nullptr);

        // tmp = ff @ ff2_w^T + b
        gemm_tf32<<<dim3(4, 32, 1), 256, GEMM_SMEM>>>(
            ff, DI, 0, 0, f2W, DI, 0, 0, f2B, tmp, DM, 0, 0, MR, DM, DI, 0,
            nullptr, nullptr, nullptr, nullptr);

        add_ln<<<MR, 128>>>(h, tmp, ln2_s + l * DM, ln2_b + l * DM);
    }

    // cls = h @ cls_w^T + b
    gemm_tf32<<<dim3(1, 32, 1), 256, GEMM_SMEM>>>(
        h, DM, 0, 0, cls_w, DM, 0, 0, cls_b, cls, NCLS, 0, 0, MR, NCLS, DM, 0,
        nullptr, nullptr, nullptr, nullptr);

    transpose_cls<<<dim3(TTT / 32, NCLS / 32, BB), dim3(32, 8)>>>(cls, outp);
}